// round 1
// baseline (speedup 1.0000x reference)
#include <cuda_runtime.h>
#include <cstdint>

#define D_DIM 1792
#define B_DIM 8192
#define NB 128
#define NBLK (D_DIM / NB)   // 14

// Scratch (device-global: no allocations allowed)
__device__ float g_Vn  [ (size_t)D_DIM * D_DIM ];
__device__ float g_G   [ (size_t)D_DIM * D_DIM ];
__device__ float g_RHS [ (size_t)D_DIM * D_DIM ];
__device__ float g_Wt  [ (size_t)D_DIM * D_DIM ];
__device__ float g_P   [ (size_t)D_DIM * D_DIM ];
__device__ float g_Tinv[ (size_t)NBLK * NB * NB ];

// ---------------------------------------------------------------------------
// Row-normalize U -> Vn, and initialize RHS = 2*Vn
// ---------------------------------------------------------------------------
__global__ void normalize_kernel(const float* __restrict__ U) {
    int row = blockIdx.x;
    const float* u = U + (size_t)row * D_DIM;
    __shared__ float red[256];
    float s = 0.f;
    for (int c = threadIdx.x; c < D_DIM; c += 256) { float v = u[c]; s += v * v; }
    red[threadIdx.x] = s;
    __syncthreads();
    for (int off = 128; off > 0; off >>= 1) {
        if (threadIdx.x < off) red[threadIdx.x] += red[threadIdx.x + off];
        __syncthreads();
    }
    float inv = rsqrtf(red[0]);
    for (int c = threadIdx.x; c < D_DIM; c += 256) {
        float v = u[c] * inv;
        g_Vn [(size_t)row * D_DIM + c] = v;
        g_RHS[(size_t)row * D_DIM + c] = 2.f * v;
    }
}

// ---------------------------------------------------------------------------
// Invert all 14 unit-lower-triangular diagonal blocks of T = I + 2*tril(G,-1)
// One CTA per block; forward substitution on the identity, fully in SMEM.
// ---------------------------------------------------------------------------
#define INV_SMEM (2 * NB * (NB + 1) * (int)sizeof(float))
__global__ void invert_diag_kernel() {
    extern __shared__ float sm[];
    float (*Gs)[NB + 1] = (float (*)[NB + 1])sm;
    float (*Zs)[NB + 1] = (float (*)[NB + 1])(sm + NB * (NB + 1));
    const int b0 = blockIdx.x * NB;
    const int tid = threadIdx.x;

    for (int idx = tid; idx < NB * NB; idx += 256) {
        int r = idx >> 7, c = idx & 127;
        Gs[r][c] = g_G[(size_t)(b0 + r) * D_DIM + b0 + c];
        Zs[r][c] = (r == c) ? 1.f : 0.f;
    }
    __syncthreads();
    for (int j = 0; j < NB - 1; ++j) {
        int rows = NB - 1 - j;
        for (int idx = tid; idx < rows * NB; idx += 256) {
            int r = j + 1 + (idx >> 7);
            int c = idx & 127;
            Zs[r][c] -= 2.f * Gs[r][j] * Zs[j][c];
        }
        __syncthreads();
    }
    float* out = g_Tinv + (size_t)blockIdx.x * NB * NB;
    for (int idx = tid; idx < NB * NB; idx += 256) {
        int r = idx >> 7, c = idx & 127;
        out[(size_t)r * NB + c] = Zs[r][c];
    }
}

// ---------------------------------------------------------------------------
// Generic tiled FP32 GEMM.
//   C[M,N] = alpha * op(A)*op(B) + beta*C  (+ I if ADDI)
//   TA=false: A is [M,K] ld=lda    TA=true: A is [K,M] ld=lda (i.e. use A^T)
//   TB=false: B is [K,N] ld=ldb    TB=true: B is [N,K] ld=ldb (i.e. use B^T)
// All M,N multiples of 128; K multiple of 16. Block 128x128x16; 8x8/thread.
// ---------------------------------------------------------------------------
template <bool TA, bool TB, bool ADDI>
__global__ void __launch_bounds__(256, 2)
sgemm_kernel(const float* __restrict__ A, const float* __restrict__ B,
             float* __restrict__ C, int M, int N, int K,
             int lda, int ldb, int ldc, float alpha, float beta)
{
    __shared__ float As[16][132];
    __shared__ float Bs[16][132];
    const int tid  = threadIdx.x;
    const int row0 = blockIdx.y * 128;
    const int col0 = blockIdx.x * 128;
    const int trow = (tid / 16) * 8;
    const int tcol = (tid % 16) * 8;

    float acc[8][8];
#pragma unroll
    for (int i = 0; i < 8; i++)
#pragma unroll
        for (int j = 0; j < 8; j++) acc[i][j] = 0.f;

    for (int k0 = 0; k0 < K; k0 += 16) {
        if (!TA) {
            // A[row, k] -> transpose into As[k][m]
#pragma unroll
            for (int l = 0; l < 2; ++l) {
                int idx = tid + l * 256;
                int m = idx >> 2, q = idx & 3;
                const float4 v = *reinterpret_cast<const float4*>(
                    &A[(size_t)(row0 + m) * lda + k0 + 4 * q]);
                As[4 * q + 0][m] = v.x; As[4 * q + 1][m] = v.y;
                As[4 * q + 2][m] = v.z; As[4 * q + 3][m] = v.w;
            }
        } else {
            // A[k, m] -> direct into As[k][m]
#pragma unroll
            for (int l = 0; l < 2; ++l) {
                int idx = tid + l * 256;
                int k = idx >> 5, mq = idx & 31;
                *reinterpret_cast<float4*>(&As[k][4 * mq]) =
                    *reinterpret_cast<const float4*>(
                        &A[(size_t)(k0 + k) * lda + row0 + 4 * mq]);
            }
        }
        if (!TB) {
            // B[k, n] -> direct into Bs[k][n]
#pragma unroll
            for (int l = 0; l < 2; ++l) {
                int idx = tid + l * 256;
                int k = idx >> 5, nq = idx & 31;
                *reinterpret_cast<float4*>(&Bs[k][4 * nq]) =
                    *reinterpret_cast<const float4*>(
                        &B[(size_t)(k0 + k) * ldb + col0 + 4 * nq]);
            }
        } else {
            // B[n, k] -> transpose into Bs[k][n]
#pragma unroll
            for (int l = 0; l < 2; ++l) {
                int idx = tid + l * 256;
                int n = idx >> 2, q = idx & 3;
                const float4 v = *reinterpret_cast<const float4*>(
                    &B[(size_t)(col0 + n) * ldb + k0 + 4 * q]);
                Bs[4 * q + 0][n] = v.x; Bs[4 * q + 1][n] = v.y;
                Bs[4 * q + 2][n] = v.z; Bs[4 * q + 3][n] = v.w;
            }
        }
        __syncthreads();

#pragma unroll
        for (int k = 0; k < 16; ++k) {
            float ar[8], br[8];
            *reinterpret_cast<float4*>(ar)     = *reinterpret_cast<float4*>(&As[k][trow]);
            *reinterpret_cast<float4*>(ar + 4) = *reinterpret_cast<float4*>(&As[k][trow + 4]);
            *reinterpret_cast<float4*>(br)     = *reinterpret_cast<float4*>(&Bs[k][tcol]);
            *reinterpret_cast<float4*>(br + 4) = *reinterpret_cast<float4*>(&Bs[k][tcol + 4]);
#pragma unroll
            for (int i = 0; i < 8; i++)
#pragma unroll
                for (int j = 0; j < 8; j++)
                    acc[i][j] += ar[i] * br[j];
        }
        __syncthreads();
    }

#pragma unroll
    for (int i = 0; i < 8; i++) {
        int gi = row0 + trow + i;
#pragma unroll
        for (int j = 0; j < 8; j++) {
            int gj = col0 + tcol + j;
            float v = alpha * acc[i][j];
            if (beta != 0.f) v += beta * C[(size_t)gi * ldc + gj];
            if (ADDI) { if (gi == gj) v += 1.f; }
            C[(size_t)gi * ldc + gj] = v;
        }
    }
}

// ---------------------------------------------------------------------------
extern "C" void kernel_launch(void* const* d_in, const int* in_sizes, int n_in,
                              void* d_out, int out_size)
{
    // metadata order: X (D*B), U (D*D). Robust to swap via sizes.
    const float* X;
    const float* U;
    if (in_sizes[0] == D_DIM * D_DIM && in_sizes[1] != D_DIM * D_DIM) {
        U = (const float*)d_in[0]; X = (const float*)d_in[1];
    } else {
        X = (const float*)d_in[0]; U = (const float*)d_in[1];
    }
    float* out = (float*)d_out;

    float *Vn, *G, *RHS, *Wt, *P, *Tinv;
    cudaGetSymbolAddress((void**)&Vn,   g_Vn);
    cudaGetSymbolAddress((void**)&G,    g_G);
    cudaGetSymbolAddress((void**)&RHS,  g_RHS);
    cudaGetSymbolAddress((void**)&Wt,   g_Wt);
    cudaGetSymbolAddress((void**)&P,    g_P);
    cudaGetSymbolAddress((void**)&Tinv, g_Tinv);

    cudaFuncSetAttribute(invert_diag_kernel,
                         cudaFuncAttributeMaxDynamicSharedMemorySize, INV_SMEM);

    // 1) Vn = normalize(U);  RHS = 2*Vn
    normalize_kernel<<<D_DIM, 256>>>(U);

    // 2) G = Vn * Vn^T   (NT)
    dim3 gDD(D_DIM / 128, D_DIM / 128);
    sgemm_kernel<false, true, false><<<gDD, 256>>>(
        Vn, Vn, G, D_DIM, D_DIM, D_DIM, D_DIM, D_DIM, D_DIM, 1.f, 0.f);

    // 3) Invert the 14 diagonal 128x128 blocks of T (parallel across blocks)
    invert_diag_kernel<<<NBLK, 256, INV_SMEM>>>();

    // 4) Blocked forward solve: T * Wt = 2*Vn
    for (int i = 0; i < NBLK; ++i) {
        // Wt[bi] = Tinv_ii @ RHS[bi]
        sgemm_kernel<false, false, false><<<dim3(D_DIM / 128, 1), 256>>>(
            Tinv + (size_t)i * NB * NB,
            RHS  + (size_t)i * NB * D_DIM,
            Wt   + (size_t)i * NB * D_DIM,
            NB, D_DIM, NB, NB, D_DIM, D_DIM, 1.f, 0.f);
        int mrem = D_DIM - (i + 1) * NB;
        if (mrem > 0) {
            // RHS[bi+1:] -= 2 * G[bi+1:, bi] @ Wt[bi]
            sgemm_kernel<false, false, false><<<dim3(D_DIM / 128, mrem / 128), 256>>>(
                G   + (size_t)((i + 1) * NB) * D_DIM + (size_t)i * NB,
                Wt  + (size_t)i * NB * D_DIM,
                RHS + (size_t)(i + 1) * NB * D_DIM,
                mrem, D_DIM, NB, D_DIM, D_DIM, D_DIM, -2.f, 1.f);
        }
    }

    // 5) P = I - Wt^T @ Vn   (TN, alpha=-1, add identity)
    sgemm_kernel<true, false, true><<<gDD, 256>>>(
        Wt, Vn, P, D_DIM, D_DIM, D_DIM, D_DIM, D_DIM, D_DIM, -1.f, 0.f);

    // 6) out = P @ X   (NN)
    sgemm_kernel<false, false, false><<<dim3(B_DIM / 128, D_DIM / 128), 256>>>(
        P, X, out, D_DIM, B_DIM, D_DIM, D_DIM, B_DIM, B_DIM, 1.f, 0.f);

    (void)n_in; (void)out_size;
}

// round 3
// speedup vs baseline: 1.7350x; 1.7350x over previous
#include <cuda_runtime.h>
#include <cuda_bf16.h>
#include <cstdint>

#define D_DIM 1792
#define B_DIM 8192
#define NB 128
#define NBLK (D_DIM / NB)   // 14

// ---------------- fp32 scratch ----------------
__device__ __align__(16) float g_Vn  [ (size_t)D_DIM * D_DIM ];
__device__ __align__(16) float g_G   [ (size_t)D_DIM * D_DIM ];
__device__ __align__(16) float g_RHS [ (size_t)D_DIM * D_DIM ];
__device__ __align__(16) float g_Wt  [ (size_t)D_DIM * D_DIM ];
__device__ __align__(16) float g_P   [ (size_t)D_DIM * D_DIM ];
__device__ __align__(16) float g_Tinv[ (size_t)NBLK * NB * NB ];

// ---------------- bf16 hi|lo scratch: [R, 2C] = [hi | lo] ----
__device__ __align__(16) __nv_bfloat16 g_Vn_hl [ (size_t)D_DIM * 2 * D_DIM ];
__device__ __align__(16) __nv_bfloat16 g_VnT_hl[ (size_t)D_DIM * 2 * D_DIM ];
__device__ __align__(16) __nv_bfloat16 g_WtT_hl[ (size_t)D_DIM * 2 * D_DIM ];
__device__ __align__(16) __nv_bfloat16 g_P_hl  [ (size_t)D_DIM * 2 * D_DIM ];
__device__ __align__(16) __nv_bfloat16 g_XT_hl [ (size_t)B_DIM * 2 * D_DIM ];

// ============================================================================
// helpers
// ============================================================================
__device__ __forceinline__ uint32_t smem_u32(const void* p) {
    uint32_t a;
    asm("{ .reg .u64 t; cvta.to.shared.u64 t, %1; cvt.u32.u64 %0, t; }"
        : "=r"(a) : "l"(p));
    return a;
}
__device__ __forceinline__ void cpa16(uint32_t s, const void* g) {
    asm volatile("cp.async.cg.shared.global [%0], [%1], 16;" :: "r"(s), "l"(g));
}
#define CPA_COMMIT() asm volatile("cp.async.commit_group;" ::: "memory")
#define CPA_WAIT(n)  asm volatile("cp.async.wait_group %0;" :: "n"(n) : "memory")

#define LDSM4(r0, r1, r2, r3, addr) \
    asm volatile("ldmatrix.sync.aligned.m8n8.x4.shared.b16 {%0,%1,%2,%3}, [%4];" \
        : "=r"(r0), "=r"(r1), "=r"(r2), "=r"(r3) : "r"(addr))

#define MMA16816(d, a, b0, b1) \
    asm volatile("mma.sync.aligned.m16n8k16.row.col.f32.bf16.bf16.f32 " \
        "{%0,%1,%2,%3}, {%4,%5,%6,%7}, {%8,%9}, {%0,%1,%2,%3};" \
        : "+f"((d)[0]), "+f"((d)[1]), "+f"((d)[2]), "+f"((d)[3]) \
        : "r"((a)[0]), "r"((a)[1]), "r"((a)[2]), "r"((a)[3]), "r"(b0), "r"(b1))

// ============================================================================
// bf16-split tensor GEMM via mma.sync:
//   C[M,N] = alpha * A @ B^T  (+ I if ADDI)
//   A: [M, 2K] bf16 (hi|lo) K-major.  B: [N, 2K] bf16 (hi|lo) K-major.
//   Fused 3-product accumulation: hh + hl + lh in fp32 registers.
//   CTA tile 128x128, 8 warps (2x4) of 64x32, k=32/stage, 4-stage cp.async.
// Shared tile layout: [128 rows][32 k] bf16, row pitch 64B, 16B chunk cc
// stored at column (cc ^ ((row>>1)&3)) -> conflict-free ldmatrix.
// ============================================================================
#define TILE_B   8192                 // one 128x32 bf16 tile
#define STAGE_B  (4 * TILE_B)         // Ah, Al, Bh, Bl
#define GEMM_SMEM (4 * STAGE_B)       // 4 stages = 131072 B

template <int ADDI>
__global__ void __launch_bounds__(256, 1)
mma_gemm(const __nv_bfloat16* __restrict__ A, const __nv_bfloat16* __restrict__ B,
         float* __restrict__ C, int K, int ldc, float alpha)
{
    extern __shared__ __align__(128) char smem[];
    const uint32_t s0 = smem_u32(smem);
    const int tid  = threadIdx.x;
    const int lane = tid & 31;
    const int wid  = tid >> 5;
    const int wm   = wid >> 2;        // 0..1
    const int wn   = wid & 3;         // 0..3
    const int row0 = blockIdx.y * 128;
    const int col0 = blockIdx.x * 128;
    const size_t ld2 = 2 * (size_t)K;
    const int T = K / 32;

    float acc[4][4][4];
#pragma unroll
    for (int i = 0; i < 4; i++)
#pragma unroll
        for (int j = 0; j < 4; j++)
#pragma unroll
            for (int q = 0; q < 4; q++) acc[i][j][q] = 0.f;

    // ---- stage loader: 4 tiles (Ah, Al, Bh, Bl), 512 chunks of 16B each ----
    auto load_stage = [&](int s) {
        const int k0 = s * 32;
        const uint32_t base = s0 + (s & 3) * STAGE_B;
        const int j = tid;            // two sub-iterations per tile
#pragma unroll
        for (int half = 0; half < 2; ++half) {
            const int jj = j + half * 256;      // 0..511
            const int r  = jj >> 2;
            const int cc = jj & 3;
            const uint32_t soff = r * 64 + ((cc ^ ((r >> 1) & 3)) << 4);
            cpa16(base + 0 * TILE_B + soff, A + (size_t)(row0 + r) * ld2 + k0 + cc * 8);
            cpa16(base + 1 * TILE_B + soff, A + (size_t)(row0 + r) * ld2 + K + k0 + cc * 8);
            cpa16(base + 2 * TILE_B + soff, B + (size_t)(col0 + r) * ld2 + k0 + cc * 8);
            cpa16(base + 3 * TILE_B + soff, B + (size_t)(col0 + r) * ld2 + K + k0 + cc * 8);
        }
        CPA_COMMIT();
    };

    load_stage(0); load_stage(1); load_stage(2);

    for (int s = 0; s < T; ++s) {
        CPA_WAIT(2);
        __syncthreads();
        if (s + 3 < T) load_stage(s + 3); else CPA_COMMIT();

        const uint32_t buf = s0 + (s & 3) * STAGE_B;
#pragma unroll
        for (int kk = 0; kk < 2; ++kk) {
            uint32_t ah[4][4], al[4][4], bh[4][2], bl[4][2];
#pragma unroll
            for (int mi = 0; mi < 4; ++mi) {
                const int row = wm * 64 + mi * 16 + ((lane >> 3) & 1) * 8 + (lane & 7);
                const int cc  = kk * 2 + (lane >> 4);
                const uint32_t off = row * 64 + ((cc ^ ((row >> 1) & 3)) << 4);
                LDSM4(ah[mi][0], ah[mi][1], ah[mi][2], ah[mi][3], buf + 0 * TILE_B + off);
                LDSM4(al[mi][0], al[mi][1], al[mi][2], al[mi][3], buf + 1 * TILE_B + off);
            }
#pragma unroll
            for (int p = 0; p < 2; ++p) {
                const int row = wn * 32 + p * 16 + (lane >> 4) * 8 + (lane & 7);
                const int cc  = kk * 2 + ((lane >> 3) & 1);
                const uint32_t off = row * 64 + ((cc ^ ((row >> 1) & 3)) << 4);
                LDSM4(bh[p * 2][0], bh[p * 2][1], bh[p * 2 + 1][0], bh[p * 2 + 1][1],
                      buf + 2 * TILE_B + off);
                LDSM4(bl[p * 2][0], bl[p * 2][1], bl[p * 2 + 1][0], bl[p * 2 + 1][1],
                      buf + 3 * TILE_B + off);
            }
#pragma unroll
            for (int mi = 0; mi < 4; ++mi)
#pragma unroll
                for (int nj = 0; nj < 4; ++nj) {
                    MMA16816(acc[mi][nj], ah[mi], bh[nj][0], bh[nj][1]);
                    MMA16816(acc[mi][nj], ah[mi], bl[nj][0], bl[nj][1]);
                    MMA16816(acc[mi][nj], al[mi], bh[nj][0], bh[nj][1]);
                }
        }
    }

    // ---- epilogue: scale, optional +I, direct float2 stores ----
    const int g = lane >> 2, t = lane & 3;
#pragma unroll
    for (int mi = 0; mi < 4; ++mi) {
#pragma unroll
        for (int nj = 0; nj < 4; ++nj) {
            const int r_ = row0 + wm * 64 + mi * 16 + g;
            const int c_ = col0 + wn * 32 + nj * 8 + 2 * t;
            float2 v;
            v.x = alpha * acc[mi][nj][0];
            v.y = alpha * acc[mi][nj][1];
            if (ADDI) { if (r_ == c_) v.x += 1.f; if (r_ == c_ + 1) v.y += 1.f; }
            *reinterpret_cast<float2*>(&C[(size_t)r_ * ldc + c_]) = v;
            v.x = alpha * acc[mi][nj][2];
            v.y = alpha * acc[mi][nj][3];
            if (ADDI) { if (r_ + 8 == c_) v.x += 1.f; if (r_ + 8 == c_ + 1) v.y += 1.f; }
            *reinterpret_cast<float2*>(&C[(size_t)(r_ + 8) * ldc + c_]) = v;
        }
    }
}

// ============================================================================
// Row-normalize U -> Vn, RHS = 2*Vn
// ============================================================================
__global__ void normalize_kernel(const float* __restrict__ U) {
    int row = blockIdx.x;
    const float* u = U + (size_t)row * D_DIM;
    __shared__ float red[256];
    float s = 0.f;
    for (int c = threadIdx.x; c < D_DIM; c += 256) { float v = u[c]; s += v * v; }
    red[threadIdx.x] = s;
    __syncthreads();
    for (int off = 128; off > 0; off >>= 1) {
        if (threadIdx.x < off) red[threadIdx.x] += red[threadIdx.x + off];
        __syncthreads();
    }
    float inv = rsqrtf(red[0]);
    for (int c = threadIdx.x; c < D_DIM; c += 256) {
        float v = u[c] * inv;
        g_Vn [(size_t)row * D_DIM + c] = v;
        g_RHS[(size_t)row * D_DIM + c] = 2.f * v;
    }
}

// ============================================================================
// fp32 -> bf16 hi|lo conversions
// ============================================================================
__global__ void conv_hl(const float* __restrict__ in, __nv_bfloat16* __restrict__ out, int C) {
    int r = blockIdx.y;
    int c = blockIdx.x * 256 + threadIdx.x;
    float x = in[(size_t)r * C + c];
    __nv_bfloat16 h = __float2bfloat16(x);
    out[(size_t)r * 2 * C + c]     = h;
    out[(size_t)r * 2 * C + C + c] = __float2bfloat16(x - __bfloat162float(h));
}
// in [R,C] -> out [C, 2R] (transpose + split)
__global__ void conv_hl_T(const float* __restrict__ in, __nv_bfloat16* __restrict__ out,
                          int R, int C) {
    __shared__ float t[32][33];
    int r0 = blockIdx.y * 32, c0 = blockIdx.x * 32;
    int tx = threadIdx.x, ty = threadIdx.y;   // 32 x 8
    for (int i = 0; i < 32; i += 8)
        t[ty + i][tx] = in[(size_t)(r0 + ty + i) * C + c0 + tx];
    __syncthreads();
    for (int i = 0; i < 32; i += 8) {
        float x = t[tx][ty + i];
        __nv_bfloat16 h = __float2bfloat16(x);
        out[(size_t)(c0 + ty + i) * 2 * R + r0 + tx]     = h;
        out[(size_t)(c0 + ty + i) * 2 * R + R + r0 + tx] =
            __float2bfloat16(x - __bfloat162float(h));
    }
}

// ============================================================================
// Diag-block inversion (unit lower tri, 128x128, one CTA each)
// ============================================================================
#define INV_SMEM (2 * NB * (NB + 1) * (int)sizeof(float))
__global__ void invert_diag_kernel() {
    extern __shared__ float sm[];
    float (*Gs)[NB + 1] = (float (*)[NB + 1])sm;
    float (*Zs)[NB + 1] = (float (*)[NB + 1])(sm + NB * (NB + 1));
    const int b0 = blockIdx.x * NB;
    const int tid = threadIdx.x;
    for (int idx = tid; idx < NB * NB; idx += 256) {
        int r = idx >> 7, c = idx & 127;
        Gs[r][c] = g_G[(size_t)(b0 + r) * D_DIM + b0 + c];
        Zs[r][c] = (r == c) ? 1.f : 0.f;
    }
    __syncthreads();
    for (int j = 0; j < NB - 1; ++j) {
        int rows = NB - 1 - j;
        for (int idx = tid; idx < rows * NB; idx += 256) {
            int r = j + 1 + (idx >> 7);
            int c = idx & 127;
            Zs[r][c] -= 2.f * Gs[r][j] * Zs[j][c];
        }
        __syncthreads();
    }
    float* out = g_Tinv + (size_t)blockIdx.x * NB * NB;
    for (int idx = tid; idx < NB * NB; idx += 256) {
        int r = idx >> 7, c = idx & 127;
        out[(size_t)r * NB + c] = Zs[r][c];
    }
}

// ============================================================================
// fp32 SGEMM for the solve chain
// ============================================================================
template <bool TA, bool TB>
__global__ void __launch_bounds__(256, 2)
sgemm_kernel(const float* __restrict__ A, const float* __restrict__ B,
             float* __restrict__ C, int M, int N, int K,
             int lda, int ldb, int ldc, float alpha, float beta)
{
    __shared__ float As[16][132];
    __shared__ float Bs[16][132];
    const int tid  = threadIdx.x;
    const int row0 = blockIdx.y * 128;
    const int col0 = blockIdx.x * 128;
    const int trow = (tid / 16) * 8;
    const int tcol = (tid % 16) * 8;
    float acc[8][8];
#pragma unroll
    for (int i = 0; i < 8; i++)
#pragma unroll
        for (int j = 0; j < 8; j++) acc[i][j] = 0.f;

    for (int k0 = 0; k0 < K; k0 += 16) {
        if (!TA) {
#pragma unroll
            for (int l = 0; l < 2; ++l) {
                int idx = tid + l * 256;
                int m = idx >> 2, q = idx & 3;
                const float4 v = *reinterpret_cast<const float4*>(
                    &A[(size_t)(row0 + m) * lda + k0 + 4 * q]);
                As[4 * q + 0][m] = v.x; As[4 * q + 1][m] = v.y;
                As[4 * q + 2][m] = v.z; As[4 * q + 3][m] = v.w;
            }
        } else {
#pragma unroll
            for (int l = 0; l < 2; ++l) {
                int idx = tid + l * 256;
                int k = idx >> 5, mq = idx & 31;
                *reinterpret_cast<float4*>(&As[k][4 * mq]) =
                    *reinterpret_cast<const float4*>(
                        &A[(size_t)(k0 + k) * lda + row0 + 4 * mq]);
            }
        }
        if (!TB) {
#pragma unroll
            for (int l = 0; l < 2; ++l) {
                int idx = tid + l * 256;
                int k = idx >> 5, nq = idx & 31;
                *reinterpret_cast<float4*>(&Bs[k][4 * nq]) =
                    *reinterpret_cast<const float4*>(
                        &B[(size_t)(k0 + k) * ldb + col0 + 4 * nq]);
            }
        } else {
#pragma unroll
            for (int l = 0; l < 2; ++l) {
                int idx = tid + l * 256;
                int n = idx >> 2, q = idx & 3;
                const float4 v = *reinterpret_cast<const float4*>(
                    &B[(size_t)(col0 + n) * ldb + k0 + 4 * q]);
                Bs[4 * q + 0][n] = v.x; Bs[4 * q + 1][n] = v.y;
                Bs[4 * q + 2][n] = v.z; Bs[4 * q + 3][n] = v.w;
            }
        }
        __syncthreads();
#pragma unroll
        for (int k = 0; k < 16; ++k) {
            float ar[8], br[8];
            *reinterpret_cast<float4*>(ar)     = *reinterpret_cast<float4*>(&As[k][trow]);
            *reinterpret_cast<float4*>(ar + 4) = *reinterpret_cast<float4*>(&As[k][trow + 4]);
            *reinterpret_cast<float4*>(br)     = *reinterpret_cast<float4*>(&Bs[k][tcol]);
            *reinterpret_cast<float4*>(br + 4) = *reinterpret_cast<float4*>(&Bs[k][tcol + 4]);
#pragma unroll
            for (int i = 0; i < 8; i++)
#pragma unroll
                for (int j = 0; j < 8; j++)
                    acc[i][j] += ar[i] * br[j];
        }
        __syncthreads();
    }
#pragma unroll
    for (int i = 0; i < 8; i++) {
        int gi = row0 + trow + i;
#pragma unroll
        for (int j = 0; j < 8; j++) {
            int gj = col0 + tcol + j;
            float v = alpha * acc[i][j];
            if (beta != 0.f) v += beta * C[(size_t)gi * ldc + gj];
            C[(size_t)gi * ldc + gj] = v;
        }
    }
}

// ============================================================================
extern "C" void kernel_launch(void* const* d_in, const int* in_sizes, int n_in,
                              void* d_out, int out_size)
{
    const float* X;
    const float* U;
    if (in_sizes[0] == D_DIM * D_DIM && in_sizes[1] != D_DIM * D_DIM) {
        U = (const float*)d_in[0]; X = (const float*)d_in[1];
    } else {
        X = (const float*)d_in[0]; U = (const float*)d_in[1];
    }
    float* out = (float*)d_out;

    float *Vn, *G, *RHS, *Wt, *P, *Tinv;
    cudaGetSymbolAddress((void**)&Vn,   g_Vn);
    cudaGetSymbolAddress((void**)&G,    g_G);
    cudaGetSymbolAddress((void**)&RHS,  g_RHS);
    cudaGetSymbolAddress((void**)&Wt,   g_Wt);
    cudaGetSymbolAddress((void**)&P,    g_P);
    cudaGetSymbolAddress((void**)&Tinv, g_Tinv);
    __nv_bfloat16 *Vn_hl, *VnT_hl, *WtT_hl, *P_hl, *XT_hl;
    cudaGetSymbolAddress((void**)&Vn_hl,  g_Vn_hl);
    cudaGetSymbolAddress((void**)&VnT_hl, g_VnT_hl);
    cudaGetSymbolAddress((void**)&WtT_hl, g_WtT_hl);
    cudaGetSymbolAddress((void**)&P_hl,   g_P_hl);
    cudaGetSymbolAddress((void**)&XT_hl,  g_XT_hl);

    cudaFuncSetAttribute(invert_diag_kernel,
                         cudaFuncAttributeMaxDynamicSharedMemorySize, INV_SMEM);
    cudaFuncSetAttribute(mma_gemm<0>,
                         cudaFuncAttributeMaxDynamicSharedMemorySize, GEMM_SMEM);
    cudaFuncSetAttribute(mma_gemm<1>,
                         cudaFuncAttributeMaxDynamicSharedMemorySize, GEMM_SMEM);

    dim3 cvt(D_DIM / 256, D_DIM);

    // X^T split-convert: [D,B] -> [B, 2D]
    conv_hl_T<<<dim3(B_DIM / 32, D_DIM / 32), dim3(32, 8)>>>(X, XT_hl, D_DIM, B_DIM);

    // 1) Vn, RHS = 2*Vn
    normalize_kernel<<<D_DIM, 256>>>(U);
    conv_hl  <<<cvt, 256>>>(Vn, Vn_hl, D_DIM);
    conv_hl_T<<<dim3(D_DIM / 32, D_DIM / 32), dim3(32, 8)>>>(Vn, VnT_hl, D_DIM, D_DIM);

    // 2) G = Vn @ Vn^T   (tensor, split bf16, fused 3-product)
    mma_gemm<0><<<dim3(D_DIM / 128, D_DIM / 128), 256, GEMM_SMEM>>>(
        Vn_hl, Vn_hl, G, D_DIM, D_DIM, 1.f);

    // 3) Invert diagonal blocks of T
    invert_diag_kernel<<<NBLK, 256, INV_SMEM>>>();

    // 4) Blocked forward solve T * Wt = 2*Vn  (fp32)
    for (int i = 0; i < NBLK; ++i) {
        sgemm_kernel<false, false><<<dim3(D_DIM / 128, 1), 256>>>(
            Tinv + (size_t)i * NB * NB,
            RHS  + (size_t)i * NB * D_DIM,
            Wt   + (size_t)i * NB * D_DIM,
            NB, D_DIM, NB, NB, D_DIM, D_DIM, 1.f, 0.f);
        int mrem = D_DIM - (i + 1) * NB;
        if (mrem > 0) {
            sgemm_kernel<false, false><<<dim3(D_DIM / 128, mrem / 128), 256>>>(
                G   + (size_t)((i + 1) * NB) * D_DIM + (size_t)i * NB,
                Wt  + (size_t)i * NB * D_DIM,
                RHS + (size_t)(i + 1) * NB * D_DIM,
                mrem, D_DIM, NB, D_DIM, D_DIM, D_DIM, -2.f, 1.f);
        }
    }

    // 5) P = I - Wt^T @ Vn
    conv_hl_T<<<dim3(D_DIM / 32, D_DIM / 32), dim3(32, 8)>>>(Wt, WtT_hl, D_DIM, D_DIM);
    mma_gemm<1><<<dim3(D_DIM / 128, D_DIM / 128), 256, GEMM_SMEM>>>(
        WtT_hl, VnT_hl, P, D_DIM, D_DIM, -1.f);

    // 6) out = P @ X
    conv_hl<<<cvt, 256>>>(P, P_hl, D_DIM);
    mma_gemm<0><<<dim3(B_DIM / 128, D_DIM / 128), 256, GEMM_SMEM>>>(
        P_hl, XT_hl, out, D_DIM, B_DIM, 1.f);

    (void)n_in; (void)out_size;
}

// round 4
// speedup vs baseline: 2.0137x; 1.1606x over previous
#include <cuda_runtime.h>
#include <cuda_bf16.h>
#include <cstdint>

#define D_DIM 1792
#define B_DIM 8192
#define NB 128
#define NBLK (D_DIM / NB)     // 14
#define NB2 256
#define NBLK2 (D_DIM / NB2)   // 7

// ---------------- fp32 scratch ----------------
__device__ __align__(16) float g_Vn   [ (size_t)D_DIM * D_DIM ];
__device__ __align__(16) float g_G    [ (size_t)D_DIM * D_DIM ];
__device__ __align__(16) float g_RHS  [ (size_t)D_DIM * D_DIM ];
__device__ __align__(16) float g_Wt   [ (size_t)D_DIM * D_DIM ];
__device__ __align__(16) float g_P    [ (size_t)D_DIM * D_DIM ];
__device__ __align__(16) float g_Tinv [ (size_t)NBLK * NB * NB ];
__device__ __align__(16) float g_Tinv2[ (size_t)NBLK2 * NB2 * NB2 ];

// ---------------- bf16 hi|lo scratch ----------------
__device__ __align__(16) __nv_bfloat16 g_Vn_hl [ (size_t)D_DIM * 2 * D_DIM ];
__device__ __align__(16) __nv_bfloat16 g_VnT_hl[ (size_t)D_DIM * 2 * D_DIM ];
__device__ __align__(16) __nv_bfloat16 g_WtT_hl[ (size_t)D_DIM * 2 * D_DIM ];
__device__ __align__(16) __nv_bfloat16 g_P_hl  [ (size_t)D_DIM * 2 * D_DIM ];
__device__ __align__(16) __nv_bfloat16 g_XT_hl [ (size_t)B_DIM * 2 * D_DIM ];

// ============================================================================
// helpers
// ============================================================================
__device__ __forceinline__ uint32_t smem_u32(const void* p) {
    uint32_t a;
    asm("{ .reg .u64 t; cvta.to.shared.u64 t, %1; cvt.u32.u64 %0, t; }"
        : "=r"(a) : "l"(p));
    return a;
}
__device__ __forceinline__ void cpa16(uint32_t s, const void* g) {
    asm volatile("cp.async.cg.shared.global [%0], [%1], 16;" :: "r"(s), "l"(g));
}
#define CPA_COMMIT() asm volatile("cp.async.commit_group;" ::: "memory")
#define CPA_WAIT(n)  asm volatile("cp.async.wait_group %0;" :: "n"(n) : "memory")

#define LDSM4(r0, r1, r2, r3, addr) \
    asm volatile("ldmatrix.sync.aligned.m8n8.x4.shared.b16 {%0,%1,%2,%3}, [%4];" \
        : "=r"(r0), "=r"(r1), "=r"(r2), "=r"(r3) : "r"(addr))

#define MMA16816(d, a, b0, b1) \
    asm volatile("mma.sync.aligned.m16n8k16.row.col.f32.bf16.bf16.f32 " \
        "{%0,%1,%2,%3}, {%4,%5,%6,%7}, {%8,%9}, {%0,%1,%2,%3};" \
        : "+f"((d)[0]), "+f"((d)[1]), "+f"((d)[2]), "+f"((d)[3]) \
        : "r"((a)[0]), "r"((a)[1]), "r"((a)[2]), "r"((a)[3]), "r"(b0), "r"(b1))

// ============================================================================
// bf16-split tensor GEMM via mma.sync:  C = alpha * A @ B^T (+I if ADDI)
//   A: [M, 2K] bf16 (hi|lo) K-major.  B: [N, 2K] bf16 (hi|lo) K-major.
//   Fused 3 products hh + lh + hl, fp32 accumulate.
//   CTA 128x128, 8 warps (2x4) of 64x32, k=32/stage, 3-stage cp.async,
//   2 CTAs/SM.  TRI=1: lower-triangular tile set only (linearized grid).
// ============================================================================
#define TILE_B   8192                 // one 128x32 bf16 tile
#define STAGE_B  (4 * TILE_B)         // Ah, Al, Bh, Bl
#define GEMM_SMEM (3 * STAGE_B)       // 3 stages = 98304 B

template <int ADDI, int TRI>
__global__ void __launch_bounds__(256, 2)
mma_gemm(const __nv_bfloat16* __restrict__ A, const __nv_bfloat16* __restrict__ B,
         float* __restrict__ C, int K, int ldc, float alpha)
{
    extern __shared__ __align__(128) char smem[];
    const uint32_t s0 = smem_u32(smem);
    const int tid  = threadIdx.x;
    const int lane = tid & 31;
    const int wid  = tid >> 5;
    const int wm   = wid >> 2;
    const int wn   = wid & 3;

    int row0, col0;
    if (TRI) {
        int bid = blockIdx.x;
        int r = 0;
        while ((r + 1) * (r + 2) / 2 <= bid) ++r;
        row0 = r * 128;
        col0 = (bid - r * (r + 1) / 2) * 128;
    } else {
        row0 = blockIdx.y * 128;
        col0 = blockIdx.x * 128;
    }
    const size_t ld2 = 2 * (size_t)K;
    const int T = K / 32;

    float acc[4][4][4];
#pragma unroll
    for (int i = 0; i < 4; i++)
#pragma unroll
        for (int j = 0; j < 4; j++)
#pragma unroll
            for (int q = 0; q < 4; q++) acc[i][j][q] = 0.f;

    auto load_stage = [&](int s) {
        const int k0 = s * 32;
        const uint32_t base = s0 + (s % 3) * STAGE_B;
#pragma unroll
        for (int half = 0; half < 2; ++half) {
            const int jj = tid + half * 256;
            const int r  = jj >> 2;
            const int cc = jj & 3;
            const uint32_t soff = r * 64 + ((cc ^ ((r >> 1) & 3)) << 4);
            cpa16(base + 0 * TILE_B + soff, A + (size_t)(row0 + r) * ld2 + k0 + cc * 8);
            cpa16(base + 1 * TILE_B + soff, A + (size_t)(row0 + r) * ld2 + K + k0 + cc * 8);
            cpa16(base + 2 * TILE_B + soff, B + (size_t)(col0 + r) * ld2 + k0 + cc * 8);
            cpa16(base + 3 * TILE_B + soff, B + (size_t)(col0 + r) * ld2 + K + k0 + cc * 8);
        }
        CPA_COMMIT();
    };

    load_stage(0); load_stage(1);

    for (int s = 0; s < T; ++s) {
        CPA_WAIT(1);
        __syncthreads();
        if (s + 2 < T) load_stage(s + 2);

        const uint32_t buf = s0 + (s % 3) * STAGE_B;
#pragma unroll
        for (int kk = 0; kk < 2; ++kk) {
            uint32_t ah[4][4], al[4][4], bb[4][2];
#pragma unroll
            for (int mi = 0; mi < 4; ++mi) {
                const int row = wm * 64 + mi * 16 + ((lane >> 3) & 1) * 8 + (lane & 7);
                const int cc  = kk * 2 + (lane >> 4);
                const uint32_t off = row * 64 + ((cc ^ ((row >> 1) & 3)) << 4);
                LDSM4(ah[mi][0], ah[mi][1], ah[mi][2], ah[mi][3], buf + 0 * TILE_B + off);
                LDSM4(al[mi][0], al[mi][1], al[mi][2], al[mi][3], buf + 1 * TILE_B + off);
            }
            // B-hi fragments
#pragma unroll
            for (int p = 0; p < 2; ++p) {
                const int row = wn * 32 + p * 16 + (lane >> 4) * 8 + (lane & 7);
                const int cc  = kk * 2 + ((lane >> 3) & 1);
                const uint32_t off = row * 64 + ((cc ^ ((row >> 1) & 3)) << 4);
                LDSM4(bb[p * 2][0], bb[p * 2][1], bb[p * 2 + 1][0], bb[p * 2 + 1][1],
                      buf + 2 * TILE_B + off);
            }
#pragma unroll
            for (int mi = 0; mi < 4; ++mi)
#pragma unroll
                for (int nj = 0; nj < 4; ++nj) {
                    MMA16816(acc[mi][nj], ah[mi], bb[nj][0], bb[nj][1]);  // hh
                    MMA16816(acc[mi][nj], al[mi], bb[nj][0], bb[nj][1]);  // lh
                }
            // B-lo fragments overwrite bb
#pragma unroll
            for (int p = 0; p < 2; ++p) {
                const int row = wn * 32 + p * 16 + (lane >> 4) * 8 + (lane & 7);
                const int cc  = kk * 2 + ((lane >> 3) & 1);
                const uint32_t off = row * 64 + ((cc ^ ((row >> 1) & 3)) << 4);
                LDSM4(bb[p * 2][0], bb[p * 2][1], bb[p * 2 + 1][0], bb[p * 2 + 1][1],
                      buf + 3 * TILE_B + off);
            }
#pragma unroll
            for (int mi = 0; mi < 4; ++mi)
#pragma unroll
                for (int nj = 0; nj < 4; ++nj)
                    MMA16816(acc[mi][nj], ah[mi], bb[nj][0], bb[nj][1]);  // hl
        }
        __syncthreads();
    }

    const int g = lane >> 2, t = lane & 3;
#pragma unroll
    for (int mi = 0; mi < 4; ++mi) {
#pragma unroll
        for (int nj = 0; nj < 4; ++nj) {
            const int r_ = row0 + wm * 64 + mi * 16 + g;
            const int c_ = col0 + wn * 32 + nj * 8 + 2 * t;
            float2 v;
            v.x = alpha * acc[mi][nj][0];
            v.y = alpha * acc[mi][nj][1];
            if (ADDI) { if (r_ == c_) v.x += 1.f; if (r_ == c_ + 1) v.y += 1.f; }
            *reinterpret_cast<float2*>(&C[(size_t)r_ * ldc + c_]) = v;
            v.x = alpha * acc[mi][nj][2];
            v.y = alpha * acc[mi][nj][3];
            if (ADDI) { if (r_ + 8 == c_) v.x += 1.f; if (r_ + 8 == c_ + 1) v.y += 1.f; }
            *reinterpret_cast<float2*>(&C[(size_t)(r_ + 8) * ldc + c_]) = v;
        }
    }
}

// ============================================================================
// Row-normalize U -> Vn, RHS = 2*Vn
// ============================================================================
__global__ void normalize_kernel(const float* __restrict__ U) {
    int row = blockIdx.x;
    const float* u = U + (size_t)row * D_DIM;
    __shared__ float red[256];
    float s = 0.f;
    for (int c = threadIdx.x; c < D_DIM; c += 256) { float v = u[c]; s += v * v; }
    red[threadIdx.x] = s;
    __syncthreads();
    for (int off = 128; off > 0; off >>= 1) {
        if (threadIdx.x < off) red[threadIdx.x] += red[threadIdx.x + off];
        __syncthreads();
    }
    float inv = rsqrtf(red[0]);
    for (int c = threadIdx.x; c < D_DIM; c += 256) {
        float v = u[c] * inv;
        g_Vn [(size_t)row * D_DIM + c] = v;
        g_RHS[(size_t)row * D_DIM + c] = 2.f * v;
    }
}

// ============================================================================
// fp32 -> bf16 hi|lo conversions
// ============================================================================
__global__ void conv_hl(const float* __restrict__ in, __nv_bfloat16* __restrict__ out, int C) {
    int r = blockIdx.y;
    int c = blockIdx.x * 256 + threadIdx.x;
    float x = in[(size_t)r * C + c];
    __nv_bfloat16 h = __float2bfloat16(x);
    out[(size_t)r * 2 * C + c]     = h;
    out[(size_t)r * 2 * C + C + c] = __float2bfloat16(x - __bfloat162float(h));
}
__global__ void conv_hl_T(const float* __restrict__ in, __nv_bfloat16* __restrict__ out,
                          int R, int C) {
    __shared__ float t[32][33];
    int r0 = blockIdx.y * 32, c0 = blockIdx.x * 32;
    int tx = threadIdx.x, ty = threadIdx.y;
    for (int i = 0; i < 32; i += 8)
        t[ty + i][tx] = in[(size_t)(r0 + ty + i) * C + c0 + tx];
    __syncthreads();
    for (int i = 0; i < 32; i += 8) {
        float x = t[tx][ty + i];
        __nv_bfloat16 h = __float2bfloat16(x);
        out[(size_t)(c0 + ty + i) * 2 * R + r0 + tx]     = h;
        out[(size_t)(c0 + ty + i) * 2 * R + R + r0 + tx] =
            __float2bfloat16(x - __bfloat162float(h));
    }
}

// ============================================================================
// Diag-block inversion (unit lower tri, 128x128, one CTA each)
// ============================================================================
#define INV_SMEM (2 * NB * (NB + 1) * (int)sizeof(float))
__global__ void invert_diag_kernel() {
    extern __shared__ float sm[];
    float (*Gs)[NB + 1] = (float (*)[NB + 1])sm;
    float (*Zs)[NB + 1] = (float (*)[NB + 1])(sm + NB * (NB + 1));
    const int b0 = blockIdx.x * NB;
    const int tid = threadIdx.x;
    for (int idx = tid; idx < NB * NB; idx += 256) {
        int r = idx >> 7, c = idx & 127;
        Gs[r][c] = g_G[(size_t)(b0 + r) * D_DIM + b0 + c];
        Zs[r][c] = (r == c) ? 1.f : 0.f;
    }
    __syncthreads();
    for (int j = 0; j < NB - 1; ++j) {
        int rows = NB - 1 - j;
        for (int idx = tid; idx < rows * NB; idx += 256) {
            int r = j + 1 + (idx >> 7);
            int c = idx & 127;
            Zs[r][c] -= 2.f * Gs[r][j] * Zs[j][c];
        }
        __syncthreads();
    }
    float* out = g_Tinv + (size_t)blockIdx.x * NB * NB;
    for (int idx = tid; idx < NB * NB; idx += 256) {
        int r = idx >> 7, c = idx & 127;
        out[(size_t)r * NB + c] = Zs[r][c];
    }
}

// ============================================================================
// Pair-combine: build 7 Tinv blocks of 256x256 from the 14 inverted 128 blocks.
//   [[A,0],[C,B]]^{-1} = [[Ai, 0], [-Bi*C*Ai, Bi]],  C = 2*G21.
//   One CTA per pair; two in-smem 128^3 fp32 GEMMs.
// ============================================================================
#define CMB_SMEM (3 * 128 * 129 * (int)sizeof(float))
__global__ void __launch_bounds__(256, 1) combine_tinv() {
    extern __shared__ float sm[];
    float (*Abuf)[129] = (float (*)[129])sm;                       // 2*G21, then Inv_b
    float (*Bbuf)[129] = (float (*)[129])(sm + 128 * 129);         // Inv_a (kept)
    float (*Tm)[129]   = (float (*)[129])(sm + 2 * 128 * 129);     // tmp
    const int p = blockIdx.x;
    const int tid = threadIdx.x;
    const int trow = (tid / 16) * 8;
    const int tcol = (tid % 16) * 8;
    const float* InvA = g_Tinv + (size_t)(2 * p)     * NB * NB;
    const float* InvB = g_Tinv + (size_t)(2 * p + 1) * NB * NB;
    const size_t g21 = (size_t)(p * 256 + 128) * D_DIM + p * 256;

    for (int idx = tid; idx < 128 * 128; idx += 256) {
        int r = idx >> 7, c = idx & 127;
        Abuf[r][c] = 2.f * g_G[g21 + (size_t)r * D_DIM + c];
        Bbuf[r][c] = InvA[idx];
    }
    __syncthreads();

    // Tm = Abuf @ Bbuf
    {
        float acc[8][8];
#pragma unroll
        for (int i = 0; i < 8; i++)
#pragma unroll
            for (int j = 0; j < 8; j++) acc[i][j] = 0.f;
        for (int k = 0; k < 128; ++k) {
            float a[8], b[8];
#pragma unroll
            for (int i = 0; i < 8; i++) a[i] = Abuf[trow + i][k];
#pragma unroll
            for (int j = 0; j < 8; j++) b[j] = Bbuf[k][tcol + j];
#pragma unroll
            for (int i = 0; i < 8; i++)
#pragma unroll
                for (int j = 0; j < 8; j++) acc[i][j] += a[i] * b[j];
        }
        __syncthreads();
#pragma unroll
        for (int i = 0; i < 8; i++)
#pragma unroll
            for (int j = 0; j < 8; j++) Tm[trow + i][tcol + j] = acc[i][j];
    }
    __syncthreads();
    // Abuf <- Inv_b
    for (int idx = tid; idx < 128 * 128; idx += 256) {
        int r = idx >> 7, c = idx & 127;
        Abuf[r][c] = InvB[idx];
    }
    __syncthreads();

    // O = -Abuf @ Tm; write assembled 256x256 block
    float* out = g_Tinv2 + (size_t)p * NB2 * NB2;
    {
        float acc[8][8];
#pragma unroll
        for (int i = 0; i < 8; i++)
#pragma unroll
            for (int j = 0; j < 8; j++) acc[i][j] = 0.f;
        for (int k = 0; k < 128; ++k) {
            float a[8], b[8];
#pragma unroll
            for (int i = 0; i < 8; i++) a[i] = Abuf[trow + i][k];
#pragma unroll
            for (int j = 0; j < 8; j++) b[j] = Tm[k][tcol + j];
#pragma unroll
            for (int i = 0; i < 8; i++)
#pragma unroll
                for (int j = 0; j < 8; j++) acc[i][j] += a[i] * b[j];
        }
#pragma unroll
        for (int i = 0; i < 8; i++) {
#pragma unroll
            for (int j = 0; j < 8; j++) {
                int r = trow + i, c = tcol + j;
                out[(size_t)r * NB2 + c]                   = Bbuf[r][c];   // Inv_a
                out[(size_t)r * NB2 + 128 + c]             = 0.f;          // upper-right
                out[(size_t)(128 + r) * NB2 + c]           = -acc[i][j];   // O
                out[(size_t)(128 + r) * NB2 + 128 + c]     = Abuf[r][c];   // Inv_b
            }
        }
    }
}

// ============================================================================
// fp32 SGEMM for the solve chain
// ============================================================================
template <bool TA, bool TB>
__global__ void __launch_bounds__(256, 2)
sgemm_kernel(const float* __restrict__ A, const float* __restrict__ B,
             float* __restrict__ C, int M, int N, int K,
             int lda, int ldb, int ldc, float alpha, float beta)
{
    __shared__ float As[16][132];
    __shared__ float Bs[16][132];
    const int tid  = threadIdx.x;
    const int row0 = blockIdx.y * 128;
    const int col0 = blockIdx.x * 128;
    const int trow = (tid / 16) * 8;
    const int tcol = (tid % 16) * 8;
    float acc[8][8];
#pragma unroll
    for (int i = 0; i < 8; i++)
#pragma unroll
        for (int j = 0; j < 8; j++) acc[i][j] = 0.f;

    for (int k0 = 0; k0 < K; k0 += 16) {
#pragma unroll
        for (int l = 0; l < 2; ++l) {
            int idx = tid + l * 256;
            int m = idx >> 2, q = idx & 3;
            const float4 v = *reinterpret_cast<const float4*>(
                &A[(size_t)(row0 + m) * lda + k0 + 4 * q]);
            As[4 * q + 0][m] = v.x; As[4 * q + 1][m] = v.y;
            As[4 * q + 2][m] = v.z; As[4 * q + 3][m] = v.w;
        }
#pragma unroll
        for (int l = 0; l < 2; ++l) {
            int idx = tid + l * 256;
            int k = idx >> 5, nq = idx & 31;
            *reinterpret_cast<float4*>(&Bs[k][4 * nq]) =
                *reinterpret_cast<const float4*>(
                    &B[(size_t)(k0 + k) * ldb + col0 + 4 * nq]);
        }
        __syncthreads();
#pragma unroll
        for (int k = 0; k < 16; ++k) {
            float ar[8], br[8];
            *reinterpret_cast<float4*>(ar)     = *reinterpret_cast<float4*>(&As[k][trow]);
            *reinterpret_cast<float4*>(ar + 4) = *reinterpret_cast<float4*>(&As[k][trow + 4]);
            *reinterpret_cast<float4*>(br)     = *reinterpret_cast<float4*>(&Bs[k][tcol]);
            *reinterpret_cast<float4*>(br + 4) = *reinterpret_cast<float4*>(&Bs[k][tcol + 4]);
#pragma unroll
            for (int i = 0; i < 8; i++)
#pragma unroll
                for (int j = 0; j < 8; j++)
                    acc[i][j] += ar[i] * br[j];
        }
        __syncthreads();
    }
#pragma unroll
    for (int i = 0; i < 8; i++) {
        int gi = row0 + trow + i;
#pragma unroll
        for (int j = 0; j < 8; j++) {
            int gj = col0 + tcol + j;
            float v = alpha * acc[i][j];
            if (beta != 0.f) v += beta * C[(size_t)gi * ldc + gj];
            C[(size_t)gi * ldc + gj] = v;
        }
    }
}

// ============================================================================
extern "C" void kernel_launch(void* const* d_in, const int* in_sizes, int n_in,
                              void* d_out, int out_size)
{
    const float* X;
    const float* U;
    if (in_sizes[0] == D_DIM * D_DIM && in_sizes[1] != D_DIM * D_DIM) {
        U = (const float*)d_in[0]; X = (const float*)d_in[1];
    } else {
        X = (const float*)d_in[0]; U = (const float*)d_in[1];
    }
    float* out = (float*)d_out;

    float *Vn, *G, *RHS, *Wt, *P, *Tinv2;
    cudaGetSymbolAddress((void**)&Vn,    g_Vn);
    cudaGetSymbolAddress((void**)&G,     g_G);
    cudaGetSymbolAddress((void**)&RHS,   g_RHS);
    cudaGetSymbolAddress((void**)&Wt,    g_Wt);
    cudaGetSymbolAddress((void**)&P,     g_P);
    cudaGetSymbolAddress((void**)&Tinv2, g_Tinv2);
    __nv_bfloat16 *Vn_hl, *VnT_hl, *WtT_hl, *P_hl, *XT_hl;
    cudaGetSymbolAddress((void**)&Vn_hl,  g_Vn_hl);
    cudaGetSymbolAddress((void**)&VnT_hl, g_VnT_hl);
    cudaGetSymbolAddress((void**)&WtT_hl, g_WtT_hl);
    cudaGetSymbolAddress((void**)&P_hl,   g_P_hl);
    cudaGetSymbolAddress((void**)&XT_hl,  g_XT_hl);

    cudaFuncSetAttribute(invert_diag_kernel,
                         cudaFuncAttributeMaxDynamicSharedMemorySize, INV_SMEM);
    cudaFuncSetAttribute(combine_tinv,
                         cudaFuncAttributeMaxDynamicSharedMemorySize, CMB_SMEM);
    cudaFuncSetAttribute(mma_gemm<0, 0>,
                         cudaFuncAttributeMaxDynamicSharedMemorySize, GEMM_SMEM);
    cudaFuncSetAttribute(mma_gemm<1, 0>,
                         cudaFuncAttributeMaxDynamicSharedMemorySize, GEMM_SMEM);
    cudaFuncSetAttribute(mma_gemm<0, 1>,
                         cudaFuncAttributeMaxDynamicSharedMemorySize, GEMM_SMEM);

    dim3 cvt(D_DIM / 256, D_DIM);

    // X^T split-convert: [D,B] -> [B, 2D]
    conv_hl_T<<<dim3(B_DIM / 32, D_DIM / 32), dim3(32, 8)>>>(X, XT_hl, D_DIM, B_DIM);

    // 1) Vn, RHS = 2*Vn
    normalize_kernel<<<D_DIM, 256>>>(U);
    conv_hl  <<<cvt, 256>>>(Vn, Vn_hl, D_DIM);
    conv_hl_T<<<dim3(D_DIM / 32, D_DIM / 32), dim3(32, 8)>>>(Vn, VnT_hl, D_DIM, D_DIM);

    // 2) G = Vn @ Vn^T — lower-triangular tiles only
    mma_gemm<0, 1><<<NBLK * (NBLK + 1) / 2, 256, GEMM_SMEM>>>(
        Vn_hl, Vn_hl, G, D_DIM, D_DIM, 1.f);

    // 3) Invert 14 diag 128-blocks; combine into 7 Tinv 256-blocks
    invert_diag_kernel<<<NBLK, 256, INV_SMEM>>>();
    combine_tinv<<<NBLK2, 256, CMB_SMEM>>>();

    // 4) Blocked forward solve T * Wt = 2*Vn  (fp32, NB2=256)
    for (int i = 0; i < NBLK2; ++i) {
        sgemm_kernel<false, false><<<dim3(D_DIM / 128, NB2 / 128), 256>>>(
            Tinv2 + (size_t)i * NB2 * NB2,
            RHS   + (size_t)i * NB2 * D_DIM,
            Wt    + (size_t)i * NB2 * D_DIM,
            NB2, D_DIM, NB2, NB2, D_DIM, D_DIM, 1.f, 0.f);
        int mrem = D_DIM - (i + 1) * NB2;
        if (mrem > 0) {
            sgemm_kernel<false, false><<<dim3(D_DIM / 128, mrem / 128), 256>>>(
                G   + (size_t)((i + 1) * NB2) * D_DIM + (size_t)i * NB2,
                Wt  + (size_t)i * NB2 * D_DIM,
                RHS + (size_t)(i + 1) * NB2 * D_DIM,
                mrem, D_DIM, NB2, D_DIM, D_DIM, D_DIM, -2.f, 1.f);
        }
    }

    // 5) P = I - Wt^T @ Vn
    conv_hl_T<<<dim3(D_DIM / 32, D_DIM / 32), dim3(32, 8)>>>(Wt, WtT_hl, D_DIM, D_DIM);
    mma_gemm<1, 0><<<dim3(D_DIM / 128, D_DIM / 128), 256, GEMM_SMEM>>>(
        WtT_hl, VnT_hl, P, D_DIM, D_DIM, -1.f);

    // 6) out = P @ X
    conv_hl<<<cvt, 256>>>(P, P_hl, D_DIM);
    mma_gemm<0, 0><<<dim3(B_DIM / 128, D_DIM / 128), 256, GEMM_SMEM>>>(
        P_hl, XT_hl, out, D_DIM, B_DIM, 1.f);

    (void)n_in; (void)out_size;
}

// round 5
// speedup vs baseline: 2.0388x; 1.0125x over previous
#include <cuda_runtime.h>
#include <cuda_bf16.h>
#include <cstdint>

#define D_DIM 1792
#define B_DIM 8192
#define NB 128
#define NBLK (D_DIM / NB)     // 14
#define NB2 256
#define NBLK2 (D_DIM / NB2)   // 7

// ---------------- fp32 scratch ----------------
__device__ __align__(16) float g_Vn   [ (size_t)D_DIM * D_DIM ];
__device__ __align__(16) float g_G    [ (size_t)D_DIM * D_DIM ];
__device__ __align__(16) float g_RHS  [ (size_t)D_DIM * D_DIM ];
__device__ __align__(16) float g_Wt   [ (size_t)D_DIM * D_DIM ];
__device__ __align__(16) float g_P    [ (size_t)D_DIM * D_DIM ];
__device__ __align__(16) float g_Tinv [ (size_t)NBLK * NB * NB ];
__device__ __align__(16) float g_Tinv2[ (size_t)NBLK2 * NB2 * NB2 ];

// ---------------- bf16 hi|lo scratch ----------------
__device__ __align__(16) __nv_bfloat16 g_Vn_hl [ (size_t)D_DIM * 2 * D_DIM ];
__device__ __align__(16) __nv_bfloat16 g_VnT_hl[ (size_t)D_DIM * 2 * D_DIM ];
__device__ __align__(16) __nv_bfloat16 g_WtT_hl[ (size_t)D_DIM * 2 * D_DIM ];
__device__ __align__(16) __nv_bfloat16 g_P_hl  [ (size_t)D_DIM * 2 * D_DIM ];
__device__ __align__(16) __nv_bfloat16 g_XT_hl [ (size_t)B_DIM * 2 * D_DIM ];

// ============================================================================
// helpers
// ============================================================================
__device__ __forceinline__ uint32_t smem_u32(const void* p) {
    uint32_t a;
    asm("{ .reg .u64 t; cvta.to.shared.u64 t, %1; cvt.u32.u64 %0, t; }"
        : "=r"(a) : "l"(p));
    return a;
}
__device__ __forceinline__ void cpa16(uint32_t s, const void* g) {
    asm volatile("cp.async.cg.shared.global [%0], [%1], 16;" :: "r"(s), "l"(g));
}
#define CPA_COMMIT() asm volatile("cp.async.commit_group;" ::: "memory")
#define CPA_WAIT(n)  asm volatile("cp.async.wait_group %0;" :: "n"(n) : "memory")

#define LDSM4(r0, r1, r2, r3, addr) \
    asm volatile("ldmatrix.sync.aligned.m8n8.x4.shared.b16 {%0,%1,%2,%3}, [%4];" \
        : "=r"(r0), "=r"(r1), "=r"(r2), "=r"(r3) : "r"(addr))

#define MMA16816(d, a, b0, b1) \
    asm volatile("mma.sync.aligned.m16n8k16.row.col.f32.bf16.bf16.f32 " \
        "{%0,%1,%2,%3}, {%4,%5,%6,%7}, {%8,%9}, {%0,%1,%2,%3};" \
        : "+f"((d)[0]), "+f"((d)[1]), "+f"((d)[2]), "+f"((d)[3]) \
        : "r"((a)[0]), "r"((a)[1]), "r"((a)[2]), "r"((a)[3]), "r"(b0), "r"(b1))

// ============================================================================
// bf16-split tensor GEMM via mma.sync:  C = alpha * A @ B^T (+I if ADDI)
//   A: [M, 2K] bf16 (hi|lo) K-major.  B: [N, 2K] bf16 (hi|lo) K-major.
//   Fused 3 products hh + lh + hl, fp32 accumulate.
//   CTA 128x128, 4 warps (2x2) of 64x64, k=32/stage, 3-stage cp.async,
//   2 CTAs/SM.  TRI=1: lower-triangular tile set only (linearized grid).
// ============================================================================
#define TILE_B   8192                 // one 128x32 bf16 tile
#define STAGE_B  (4 * TILE_B)         // Ah, Al, Bh, Bl
#define GEMM_SMEM (3 * STAGE_B)       // 3 stages = 98304 B
#define GEMM_THR 128

template <int ADDI, int TRI>
__global__ void __launch_bounds__(GEMM_THR, 2)
mma_gemm(const __nv_bfloat16* __restrict__ A, const __nv_bfloat16* __restrict__ B,
         float* __restrict__ C, int K, int ldc, float alpha)
{
    extern __shared__ __align__(128) char smem[];
    const uint32_t s0 = smem_u32(smem);
    const int tid  = threadIdx.x;
    const int lane = tid & 31;
    const int wid  = tid >> 5;        // 0..3
    const int wm   = wid >> 1;        // 0..1
    const int wn   = wid & 1;         // 0..1

    int row0, col0;
    if (TRI) {
        int bid = blockIdx.x;
        int r = 0;
        while ((r + 1) * (r + 2) / 2 <= bid) ++r;
        row0 = r * 128;
        col0 = (bid - r * (r + 1) / 2) * 128;
    } else {
        row0 = blockIdx.y * 128;
        col0 = blockIdx.x * 128;
    }
    const size_t ld2 = 2 * (size_t)K;
    const int T = K / 32;

    float acc[4][8][4];
#pragma unroll
    for (int i = 0; i < 4; i++)
#pragma unroll
        for (int j = 0; j < 8; j++)
#pragma unroll
            for (int q = 0; q < 4; q++) acc[i][j][q] = 0.f;

    auto load_stage = [&](int s) {
        const int k0 = s * 32;
        const uint32_t base = s0 + (s % 3) * STAGE_B;
#pragma unroll
        for (int qq = 0; qq < 4; ++qq) {
            const int jj = tid + qq * GEMM_THR;     // 0..511
            const int r  = jj >> 2;
            const int cc = jj & 3;
            const uint32_t soff = r * 64 + ((cc ^ ((r >> 1) & 3)) << 4);
            cpa16(base + 0 * TILE_B + soff, A + (size_t)(row0 + r) * ld2 + k0 + cc * 8);
            cpa16(base + 1 * TILE_B + soff, A + (size_t)(row0 + r) * ld2 + K + k0 + cc * 8);
            cpa16(base + 2 * TILE_B + soff, B + (size_t)(col0 + r) * ld2 + k0 + cc * 8);
            cpa16(base + 3 * TILE_B + soff, B + (size_t)(col0 + r) * ld2 + K + k0 + cc * 8);
        }
        CPA_COMMIT();
    };

    load_stage(0); load_stage(1);

    for (int s = 0; s < T; ++s) {
        CPA_WAIT(1);
        __syncthreads();
        if (s + 2 < T) load_stage(s + 2);

        const uint32_t buf = s0 + (s % 3) * STAGE_B;
#pragma unroll
        for (int kk = 0; kk < 2; ++kk) {
            uint32_t ah[4][4], al[4][4], bb[8][2];
#pragma unroll
            for (int mi = 0; mi < 4; ++mi) {
                const int row = wm * 64 + mi * 16 + ((lane >> 3) & 1) * 8 + (lane & 7);
                const int cc  = kk * 2 + (lane >> 4);
                const uint32_t off = row * 64 + ((cc ^ ((row >> 1) & 3)) << 4);
                LDSM4(ah[mi][0], ah[mi][1], ah[mi][2], ah[mi][3], buf + 0 * TILE_B + off);
                LDSM4(al[mi][0], al[mi][1], al[mi][2], al[mi][3], buf + 1 * TILE_B + off);
            }
            // B-hi fragments (64 cols = 8 n-blocks via 4 LDSM.x4)
#pragma unroll
            for (int p = 0; p < 4; ++p) {
                const int row = wn * 64 + p * 16 + (lane >> 4) * 8 + (lane & 7);
                const int cc  = kk * 2 + ((lane >> 3) & 1);
                const uint32_t off = row * 64 + ((cc ^ ((row >> 1) & 3)) << 4);
                LDSM4(bb[p * 2][0], bb[p * 2][1], bb[p * 2 + 1][0], bb[p * 2 + 1][1],
                      buf + 2 * TILE_B + off);
            }
#pragma unroll
            for (int mi = 0; mi < 4; ++mi)
#pragma unroll
                for (int nj = 0; nj < 8; ++nj) {
                    MMA16816(acc[mi][nj], ah[mi], bb[nj][0], bb[nj][1]);  // hh
                    MMA16816(acc[mi][nj], al[mi], bb[nj][0], bb[nj][1]);  // lh
                }
            // B-lo fragments overwrite bb
#pragma unroll
            for (int p = 0; p < 4; ++p) {
                const int row = wn * 64 + p * 16 + (lane >> 4) * 8 + (lane & 7);
                const int cc  = kk * 2 + ((lane >> 3) & 1);
                const uint32_t off = row * 64 + ((cc ^ ((row >> 1) & 3)) << 4);
                LDSM4(bb[p * 2][0], bb[p * 2][1], bb[p * 2 + 1][0], bb[p * 2 + 1][1],
                      buf + 3 * TILE_B + off);
            }
#pragma unroll
            for (int mi = 0; mi < 4; ++mi)
#pragma unroll
                for (int nj = 0; nj < 8; ++nj)
                    MMA16816(acc[mi][nj], ah[mi], bb[nj][0], bb[nj][1]);  // hl
        }
    }

    const int g = lane >> 2, t = lane & 3;
#pragma unroll
    for (int mi = 0; mi < 4; ++mi) {
#pragma unroll
        for (int nj = 0; nj < 8; ++nj) {
            const int r_ = row0 + wm * 64 + mi * 16 + g;
            const int c_ = col0 + wn * 64 + nj * 8 + 2 * t;
            float2 v;
            v.x = alpha * acc[mi][nj][0];
            v.y = alpha * acc[mi][nj][1];
            if (ADDI) { if (r_ == c_) v.x += 1.f; if (r_ == c_ + 1) v.y += 1.f; }
            *reinterpret_cast<float2*>(&C[(size_t)r_ * ldc + c_]) = v;
            v.x = alpha * acc[mi][nj][2];
            v.y = alpha * acc[mi][nj][3];
            if (ADDI) { if (r_ + 8 == c_) v.x += 1.f; if (r_ + 8 == c_ + 1) v.y += 1.f; }
            *reinterpret_cast<float2*>(&C[(size_t)(r_ + 8) * ldc + c_]) = v;
        }
    }
}

// ============================================================================
// Row-normalize U -> Vn, RHS = 2*Vn
// ============================================================================
__global__ void normalize_kernel(const float* __restrict__ U) {
    int row = blockIdx.x;
    const float* u = U + (size_t)row * D_DIM;
    __shared__ float red[256];
    float s = 0.f;
    for (int c = threadIdx.x; c < D_DIM; c += 256) { float v = u[c]; s += v * v; }
    red[threadIdx.x] = s;
    __syncthreads();
    for (int off = 128; off > 0; off >>= 1) {
        if (threadIdx.x < off) red[threadIdx.x] += red[threadIdx.x + off];
        __syncthreads();
    }
    float inv = rsqrtf(red[0]);
    for (int c = threadIdx.x; c < D_DIM; c += 256) {
        float v = u[c] * inv;
        g_Vn [(size_t)row * D_DIM + c] = v;
        g_RHS[(size_t)row * D_DIM + c] = 2.f * v;
    }
}

// ============================================================================
// fp32 -> bf16 hi|lo conversions
// ============================================================================
__global__ void conv_hl(const float* __restrict__ in, __nv_bfloat16* __restrict__ out, int C) {
    int r = blockIdx.y;
    int c = blockIdx.x * 256 + threadIdx.x;
    float x = in[(size_t)r * C + c];
    __nv_bfloat16 h = __float2bfloat16(x);
    out[(size_t)r * 2 * C + c]     = h;
    out[(size_t)r * 2 * C + C + c] = __float2bfloat16(x - __bfloat162float(h));
}
__global__ void conv_hl_T(const float* __restrict__ in, __nv_bfloat16* __restrict__ out,
                          int R, int C) {
    __shared__ float t[32][33];
    int r0 = blockIdx.y * 32, c0 = blockIdx.x * 32;
    int tx = threadIdx.x, ty = threadIdx.y;
    for (int i = 0; i < 32; i += 8)
        t[ty + i][tx] = in[(size_t)(r0 + ty + i) * C + c0 + tx];
    __syncthreads();
    for (int i = 0; i < 32; i += 8) {
        float x = t[tx][ty + i];
        __nv_bfloat16 h = __float2bfloat16(x);
        out[(size_t)(c0 + ty + i) * 2 * R + r0 + tx]     = h;
        out[(size_t)(c0 + ty + i) * 2 * R + R + r0 + tx] =
            __float2bfloat16(x - __bfloat162float(h));
    }
}

// ============================================================================
// Diag-block inversion (unit lower tri, 128x128, one CTA each)
// ============================================================================
#define INV_SMEM (2 * NB * (NB + 1) * (int)sizeof(float))
__global__ void invert_diag_kernel() {
    extern __shared__ float sm[];
    float (*Gs)[NB + 1] = (float (*)[NB + 1])sm;
    float (*Zs)[NB + 1] = (float (*)[NB + 1])(sm + NB * (NB + 1));
    const int b0 = blockIdx.x * NB;
    const int tid = threadIdx.x;
    for (int idx = tid; idx < NB * NB; idx += 256) {
        int r = idx >> 7, c = idx & 127;
        Gs[r][c] = g_G[(size_t)(b0 + r) * D_DIM + b0 + c];
        Zs[r][c] = (r == c) ? 1.f : 0.f;
    }
    __syncthreads();
    for (int j = 0; j < NB - 1; ++j) {
        int rows = NB - 1 - j;
        for (int idx = tid; idx < rows * NB; idx += 256) {
            int r = j + 1 + (idx >> 7);
            int c = idx & 127;
            Zs[r][c] -= 2.f * Gs[r][j] * Zs[j][c];
        }
        __syncthreads();
    }
    float* out = g_Tinv + (size_t)blockIdx.x * NB * NB;
    for (int idx = tid; idx < NB * NB; idx += 256) {
        int r = idx >> 7, c = idx & 127;
        out[(size_t)r * NB + c] = Zs[r][c];
    }
}

// ============================================================================
// Pair-combine: 7 Tinv2 blocks (256x256) from 14 inverted 128 blocks.
// ============================================================================
#define CMB_SMEM (3 * 128 * 129 * (int)sizeof(float))
__global__ void __launch_bounds__(256, 1) combine_tinv() {
    extern __shared__ float sm[];
    float (*Abuf)[129] = (float (*)[129])sm;
    float (*Bbuf)[129] = (float (*)[129])(sm + 128 * 129);
    float (*Tm)[129]   = (float (*)[129])(sm + 2 * 128 * 129);
    const int p = blockIdx.x;
    const int tid = threadIdx.x;
    const int trow = (tid / 16) * 8;
    const int tcol = (tid % 16) * 8;
    const float* InvA = g_Tinv + (size_t)(2 * p)     * NB * NB;
    const float* InvB = g_Tinv + (size_t)(2 * p + 1) * NB * NB;
    const size_t g21 = (size_t)(p * 256 + 128) * D_DIM + p * 256;

    for (int idx = tid; idx < 128 * 128; idx += 256) {
        int r = idx >> 7, c = idx & 127;
        Abuf[r][c] = 2.f * g_G[g21 + (size_t)r * D_DIM + c];
        Bbuf[r][c] = InvA[idx];
    }
    __syncthreads();
    {
        float acc[8][8];
#pragma unroll
        for (int i = 0; i < 8; i++)
#pragma unroll
            for (int j = 0; j < 8; j++) acc[i][j] = 0.f;
        for (int k = 0; k < 128; ++k) {
            float a[8], b[8];
#pragma unroll
            for (int i = 0; i < 8; i++) a[i] = Abuf[trow + i][k];
#pragma unroll
            for (int j = 0; j < 8; j++) b[j] = Bbuf[k][tcol + j];
#pragma unroll
            for (int i = 0; i < 8; i++)
#pragma unroll
                for (int j = 0; j < 8; j++) acc[i][j] += a[i] * b[j];
        }
        __syncthreads();
#pragma unroll
        for (int i = 0; i < 8; i++)
#pragma unroll
            for (int j = 0; j < 8; j++) Tm[trow + i][tcol + j] = acc[i][j];
    }
    __syncthreads();
    for (int idx = tid; idx < 128 * 128; idx += 256) {
        int r = idx >> 7, c = idx & 127;
        Abuf[r][c] = InvB[idx];
    }
    __syncthreads();
    float* out = g_Tinv2 + (size_t)p * NB2 * NB2;
    {
        float acc[8][8];
#pragma unroll
        for (int i = 0; i < 8; i++)
#pragma unroll
            for (int j = 0; j < 8; j++) acc[i][j] = 0.f;
        for (int k = 0; k < 128; ++k) {
            float a[8], b[8];
#pragma unroll
            for (int i = 0; i < 8; i++) a[i] = Abuf[trow + i][k];
#pragma unroll
            for (int j = 0; j < 8; j++) b[j] = Tm[k][tcol + j];
#pragma unroll
            for (int i = 0; i < 8; i++)
#pragma unroll
                for (int j = 0; j < 8; j++) acc[i][j] += a[i] * b[j];
        }
#pragma unroll
        for (int i = 0; i < 8; i++) {
#pragma unroll
            for (int j = 0; j < 8; j++) {
                int r = trow + i, c = tcol + j;
                out[(size_t)r * NB2 + c]               = Bbuf[r][c];
                out[(size_t)r * NB2 + 128 + c]         = 0.f;
                out[(size_t)(128 + r) * NB2 + c]       = -acc[i][j];
                out[(size_t)(128 + r) * NB2 + 128 + c] = Abuf[r][c];
            }
        }
    }
}

// ============================================================================
// fp32 SGEMM for the solve chain
// ============================================================================
template <bool TA, bool TB>
__global__ void __launch_bounds__(256, 2)
sgemm_kernel(const float* __restrict__ A, const float* __restrict__ B,
             float* __restrict__ C, int M, int N, int K,
             int lda, int ldb, int ldc, float alpha, float beta)
{
    __shared__ float As[16][132];
    __shared__ float Bs[16][132];
    const int tid  = threadIdx.x;
    const int row0 = blockIdx.y * 128;
    const int col0 = blockIdx.x * 128;
    const int trow = (tid / 16) * 8;
    const int tcol = (tid % 16) * 8;
    float acc[8][8];
#pragma unroll
    for (int i = 0; i < 8; i++)
#pragma unroll
        for (int j = 0; j < 8; j++) acc[i][j] = 0.f;

    for (int k0 = 0; k0 < K; k0 += 16) {
#pragma unroll
        for (int l = 0; l < 2; ++l) {
            int idx = tid + l * 256;
            int m = idx >> 2, q = idx & 3;
            const float4 v = *reinterpret_cast<const float4*>(
                &A[(size_t)(row0 + m) * lda + k0 + 4 * q]);
            As[4 * q + 0][m] = v.x; As[4 * q + 1][m] = v.y;
            As[4 * q + 2][m] = v.z; As[4 * q + 3][m] = v.w;
        }
#pragma unroll
        for (int l = 0; l < 2; ++l) {
            int idx = tid + l * 256;
            int k = idx >> 5, nq = idx & 31;
            *reinterpret_cast<float4*>(&Bs[k][4 * nq]) =
                *reinterpret_cast<const float4*>(
                    &B[(size_t)(k0 + k) * ldb + col0 + 4 * nq]);
        }
        __syncthreads();
#pragma unroll
        for (int k = 0; k < 16; ++k) {
            float ar[8], br[8];
            *reinterpret_cast<float4*>(ar)     = *reinterpret_cast<float4*>(&As[k][trow]);
            *reinterpret_cast<float4*>(ar + 4) = *reinterpret_cast<float4*>(&As[k][trow + 4]);
            *reinterpret_cast<float4*>(br)     = *reinterpret_cast<float4*>(&Bs[k][tcol]);
            *reinterpret_cast<float4*>(br + 4) = *reinterpret_cast<float4*>(&Bs[k][tcol + 4]);
#pragma unroll
            for (int i = 0; i < 8; i++)
#pragma unroll
                for (int j = 0; j < 8; j++)
                    acc[i][j] += ar[i] * br[j];
        }
        __syncthreads();
    }
#pragma unroll
    for (int i = 0; i < 8; i++) {
        int gi = row0 + trow + i;
#pragma unroll
        for (int j = 0; j < 8; j++) {
            int gj = col0 + tcol + j;
            float v = alpha * acc[i][j];
            if (beta != 0.f) v += beta * C[(size_t)gi * ldc + gj];
            C[(size_t)gi * ldc + gj] = v;
        }
    }
}

// ============================================================================
extern "C" void kernel_launch(void* const* d_in, const int* in_sizes, int n_in,
                              void* d_out, int out_size)
{
    const float* X;
    const float* U;
    if (in_sizes[0] == D_DIM * D_DIM && in_sizes[1] != D_DIM * D_DIM) {
        U = (const float*)d_in[0]; X = (const float*)d_in[1];
    } else {
        X = (const float*)d_in[0]; U = (const float*)d_in[1];
    }
    float* out = (float*)d_out;

    float *Vn, *G, *RHS, *Wt, *P, *Tinv2;
    cudaGetSymbolAddress((void**)&Vn,    g_Vn);
    cudaGetSymbolAddress((void**)&G,     g_G);
    cudaGetSymbolAddress((void**)&RHS,   g_RHS);
    cudaGetSymbolAddress((void**)&Wt,    g_Wt);
    cudaGetSymbolAddress((void**)&P,     g_P);
    cudaGetSymbolAddress((void**)&Tinv2, g_Tinv2);
    __nv_bfloat16 *Vn_hl, *VnT_hl, *WtT_hl, *P_hl, *XT_hl;
    cudaGetSymbolAddress((void**)&Vn_hl,  g_Vn_hl);
    cudaGetSymbolAddress((void**)&VnT_hl, g_VnT_hl);
    cudaGetSymbolAddress((void**)&WtT_hl, g_WtT_hl);
    cudaGetSymbolAddress((void**)&P_hl,   g_P_hl);
    cudaGetSymbolAddress((void**)&XT_hl,  g_XT_hl);

    cudaFuncSetAttribute(invert_diag_kernel,
                         cudaFuncAttributeMaxDynamicSharedMemorySize, INV_SMEM);
    cudaFuncSetAttribute(combine_tinv,
                         cudaFuncAttributeMaxDynamicSharedMemorySize, CMB_SMEM);
    cudaFuncSetAttribute(mma_gemm<0, 0>,
                         cudaFuncAttributeMaxDynamicSharedMemorySize, GEMM_SMEM);
    cudaFuncSetAttribute(mma_gemm<1, 0>,
                         cudaFuncAttributeMaxDynamicSharedMemorySize, GEMM_SMEM);
    cudaFuncSetAttribute(mma_gemm<0, 1>,
                         cudaFuncAttributeMaxDynamicSharedMemorySize, GEMM_SMEM);

    dim3 cvt(D_DIM / 256, D_DIM);

    // X^T split-convert: [D,B] -> [B, 2D]
    conv_hl_T<<<dim3(B_DIM / 32, D_DIM / 32), dim3(32, 8)>>>(X, XT_hl, D_DIM, B_DIM);

    // 1) Vn, RHS = 2*Vn
    normalize_kernel<<<D_DIM, 256>>>(U);
    conv_hl  <<<cvt, 256>>>(Vn, Vn_hl, D_DIM);
    conv_hl_T<<<dim3(D_DIM / 32, D_DIM / 32), dim3(32, 8)>>>(Vn, VnT_hl, D_DIM, D_DIM);

    // 2) G = Vn @ Vn^T — lower-triangular tiles only
    mma_gemm<0, 1><<<NBLK * (NBLK + 1) / 2, GEMM_THR, GEMM_SMEM>>>(
        Vn_hl, Vn_hl, G, D_DIM, D_DIM, 1.f);

    // 3) Invert 14 diag 128-blocks; combine into 7 Tinv 256-blocks
    invert_diag_kernel<<<NBLK, 256, INV_SMEM>>>();
    combine_tinv<<<NBLK2, 256, CMB_SMEM>>>();

    // 4) Blocked forward solve T * Wt = 2*Vn  (fp32, NB2=256)
    for (int i = 0; i < NBLK2; ++i) {
        sgemm_kernel<false, false><<<dim3(D_DIM / 128, NB2 / 128), 256>>>(
            Tinv2 + (size_t)i * NB2 * NB2,
            RHS   + (size_t)i * NB2 * D_DIM,
            Wt    + (size_t)i * NB2 * D_DIM,
            NB2, D_DIM, NB2, NB2, D_DIM, D_DIM, 1.f, 0.f);
        int mrem = D_DIM - (i + 1) * NB2;
        if (mrem > 0) {
            sgemm_kernel<false, false><<<dim3(D_DIM / 128, mrem / 128), 256>>>(
                G   + (size_t)((i + 1) * NB2) * D_DIM + (size_t)i * NB2,
                Wt  + (size_t)i * NB2 * D_DIM,
                RHS + (size_t)(i + 1) * NB2 * D_DIM,
                mrem, D_DIM, NB2, D_DIM, D_DIM, D_DIM, -2.f, 1.f);
        }
    }

    // 5) P = I - Wt^T @ Vn
    conv_hl_T<<<dim3(D_DIM / 32, D_DIM / 32), dim3(32, 8)>>>(Wt, WtT_hl, D_DIM, D_DIM);
    mma_gemm<1, 0><<<dim3(D_DIM / 128, D_DIM / 128), GEMM_THR, GEMM_SMEM>>>(
        WtT_hl, VnT_hl, P, D_DIM, D_DIM, -1.f);

    // 6) out = P @ X
    conv_hl<<<cvt, 256>>>(P, P_hl, D_DIM);
    mma_gemm<0, 0><<<dim3(B_DIM / 128, D_DIM / 128), GEMM_THR, GEMM_SMEM>>>(
        P_hl, XT_hl, out, D_DIM, B_DIM, 1.f);

    (void)n_in; (void)out_size;
}

// round 6
// speedup vs baseline: 2.7729x; 1.3601x over previous
#include <cuda_runtime.h>
#include <cuda_bf16.h>
#include <cstdint>

#define D_DIM 1792
#define B_DIM 8192
#define NB 128
#define NBLK (D_DIM / NB)     // 14
#define NB2 256
#define NBLK2 (D_DIM / NB2)   // 7
#define MREM0 1536            // largest trailing M in the chain

// ---------------- fp32 scratch ----------------
__device__ __align__(16) float g_Vn   [ (size_t)D_DIM * D_DIM ];
__device__ __align__(16) float g_G    [ (size_t)D_DIM * D_DIM ];
__device__ __align__(16) float g_RHS  [ (size_t)D_DIM * D_DIM ];
__device__ __align__(16) float g_Wt   [ (size_t)D_DIM * D_DIM ];
__device__ __align__(16) float g_P    [ (size_t)D_DIM * D_DIM ];
__device__ __align__(16) float g_Tinv [ (size_t)NBLK * NB * NB ];
__device__ __align__(16) float g_Tinv2[ (size_t)NBLK2 * NB2 * NB2 ];
__device__ __align__(16) float g_S    [ (size_t)(NBLK2 - 1) * MREM0 * NB2 ];

// ---------------- bf16 hi|lo scratch ----------------
__device__ __align__(16) __nv_bfloat16 g_Vn_hl    [ (size_t)D_DIM * 2 * D_DIM ];
__device__ __align__(16) __nv_bfloat16 g_VnT_hl   [ (size_t)D_DIM * 2 * D_DIM ];
__device__ __align__(16) __nv_bfloat16 g_G_hl     [ (size_t)D_DIM * 2 * D_DIM ];
__device__ __align__(16) __nv_bfloat16 g_WtT_hl   [ (size_t)D_DIM * 2 * D_DIM ];
__device__ __align__(16) __nv_bfloat16 g_RHST_hl  [ (size_t)D_DIM * 2 * D_DIM ];
__device__ __align__(16) __nv_bfloat16 g_P_hl     [ (size_t)D_DIM * 2 * D_DIM ];
__device__ __align__(16) __nv_bfloat16 g_XT_hl    [ (size_t)B_DIM * 2 * D_DIM ];
__device__ __align__(16) __nv_bfloat16 g_Tinv2_hl [ (size_t)NBLK2 * NB2 * 2 * NB2 ];
__device__ __align__(16) __nv_bfloat16 g_Tinv2T_hl[ (size_t)NBLK2 * NB2 * 2 * NB2 ];
__device__ __align__(16) __nv_bfloat16 g_S_hl     [ (size_t)(NBLK2 - 1) * MREM0 * 2 * NB2 ];

// ============================================================================
// helpers
// ============================================================================
__device__ __forceinline__ uint32_t smem_u32(const void* p) {
    uint32_t a;
    asm("{ .reg .u64 t; cvta.to.shared.u64 t, %1; cvt.u32.u64 %0, t; }"
        : "=r"(a) : "l"(p));
    return a;
}
__device__ __forceinline__ void cpa16(uint32_t s, const void* g) {
    asm volatile("cp.async.cg.shared.global [%0], [%1], 16;" :: "r"(s), "l"(g));
}
#define CPA_COMMIT() asm volatile("cp.async.commit_group;" ::: "memory")
#define CPA_WAIT(n)  asm volatile("cp.async.wait_group %0;" :: "n"(n) : "memory")

#define LDSM4(r0, r1, r2, r3, addr) \
    asm volatile("ldmatrix.sync.aligned.m8n8.x4.shared.b16 {%0,%1,%2,%3}, [%4];" \
        : "=r"(r0), "=r"(r1), "=r"(r2), "=r"(r3) : "r"(addr))

#define MMA16816(d, a, b0, b1) \
    asm volatile("mma.sync.aligned.m16n8k16.row.col.f32.bf16.bf16.f32 " \
        "{%0,%1,%2,%3}, {%4,%5,%6,%7}, {%8,%9}, {%0,%1,%2,%3};" \
        : "+f"((d)[0]), "+f"((d)[1]), "+f"((d)[2]), "+f"((d)[3]) \
        : "r"((a)[0]), "r"((a)[1]), "r"((a)[2]), "r"((a)[3]), "r"(b0), "r"(b1))

// ============================================================================
// Generalized bf16-split tensor GEMM:  C = alpha * A @ B^T (+ C if BETA) (+I if ADDI)
//   A hi at A[(m)*lda2 + k], lo at + loA.   B hi at B[(n)*ldb2 + k], lo at + loB.
//   TRI:   lower-triangular tile set, linearized blockIdx.x
//   BDIAG: A is block-diagonal 256-blocks (also shifts B's k-slice per block)
//   ZB:    z-batched (A/B/C strides zAs/zBs/zCs, M = M0 - dM*z)
//   CTA 128x128, 4 warps of 64x64, k=32/stage, 3-stage cp.async, 2 CTAs/SM.
// ============================================================================
#define TILE_B   8192
#define STAGE_B  (4 * TILE_B)
#define GEMM_SMEM (3 * STAGE_B)
#define GEMM_THR 128

template <int ADDI, int TRI, int BETA, int BDIAG, int ZB>
__global__ void __launch_bounds__(GEMM_THR, 2)
mma_gemm(const __nv_bfloat16* __restrict__ A, const __nv_bfloat16* __restrict__ B,
         float* __restrict__ C, int K, int lda2, int loA, int ldb2, int loB,
         int ldc, float alpha,
         long long zAs, long long zBs, long long zCs, int M0, int dM)
{
    extern __shared__ __align__(128) char smem[];
    const uint32_t s0 = smem_u32(smem);
    const int tid  = threadIdx.x;
    const int lane = tid & 31;
    const int wid  = tid >> 5;
    const int wm   = wid >> 1;
    const int wn   = wid & 1;

    if (ZB) {
        const int z = blockIdx.z;
        A += zAs * z; B += zBs * z; C += zCs * z;
        if ((int)(blockIdx.y * 128) >= M0 - dM * z) return;
    }

    int row0, col0;
    if (TRI) {
        int bid = blockIdx.x;
        int r = 0;
        while ((r + 1) * (r + 2) / 2 <= bid) ++r;
        row0 = r * 128;
        col0 = (bid - r * (r + 1) / 2) * 128;
    } else {
        row0 = blockIdx.y * 128;
        col0 = blockIdx.x * 128;
    }

    const __nv_bfloat16* Ap = A;
    const __nv_bfloat16* Bp = B;
    int rowA0 = row0;
    if (BDIAG) {
        const int bi = row0 >> 8;
        Ap += (size_t)bi * 256 * lda2;
        Bp += bi * 256;
        rowA0 = row0 & 255;
    }
    const int T = K / 32;

    float acc[4][8][4];
#pragma unroll
    for (int i = 0; i < 4; i++)
#pragma unroll
        for (int j = 0; j < 8; j++)
#pragma unroll
            for (int q = 0; q < 4; q++) acc[i][j][q] = 0.f;

    auto load_stage = [&](int s) {
        const int k0 = s * 32;
        const uint32_t base = s0 + (s % 3) * STAGE_B;
#pragma unroll
        for (int qq = 0; qq < 4; ++qq) {
            const int jj = tid + qq * GEMM_THR;     // 0..511
            const int r  = jj >> 2;
            const int cc = jj & 3;
            const uint32_t soff = r * 64 + ((cc ^ ((r >> 1) & 3)) << 4);
            const __nv_bfloat16* ag = Ap + (size_t)(rowA0 + r) * lda2 + k0 + cc * 8;
            const __nv_bfloat16* bg = Bp + (size_t)(col0 + r) * ldb2 + k0 + cc * 8;
            cpa16(base + 0 * TILE_B + soff, ag);
            cpa16(base + 1 * TILE_B + soff, ag + loA);
            cpa16(base + 2 * TILE_B + soff, bg);
            cpa16(base + 3 * TILE_B + soff, bg + loB);
        }
        CPA_COMMIT();
    };

    load_stage(0); load_stage(1);

    for (int s = 0; s < T; ++s) {
        CPA_WAIT(1);
        __syncthreads();
        if (s + 2 < T) load_stage(s + 2);

        const uint32_t buf = s0 + (s % 3) * STAGE_B;
#pragma unroll
        for (int kk = 0; kk < 2; ++kk) {
            uint32_t ah[4][4], al[4][4], bb[8][2];
#pragma unroll
            for (int mi = 0; mi < 4; ++mi) {
                const int row = wm * 64 + mi * 16 + ((lane >> 3) & 1) * 8 + (lane & 7);
                const int cc  = kk * 2 + (lane >> 4);
                const uint32_t off = row * 64 + ((cc ^ ((row >> 1) & 3)) << 4);
                LDSM4(ah[mi][0], ah[mi][1], ah[mi][2], ah[mi][3], buf + 0 * TILE_B + off);
                LDSM4(al[mi][0], al[mi][1], al[mi][2], al[mi][3], buf + 1 * TILE_B + off);
            }
#pragma unroll
            for (int p = 0; p < 4; ++p) {
                const int row = wn * 64 + p * 16 + (lane >> 4) * 8 + (lane & 7);
                const int cc  = kk * 2 + ((lane >> 3) & 1);
                const uint32_t off = row * 64 + ((cc ^ ((row >> 1) & 3)) << 4);
                LDSM4(bb[p * 2][0], bb[p * 2][1], bb[p * 2 + 1][0], bb[p * 2 + 1][1],
                      buf + 2 * TILE_B + off);
            }
#pragma unroll
            for (int mi = 0; mi < 4; ++mi)
#pragma unroll
                for (int nj = 0; nj < 8; ++nj) {
                    MMA16816(acc[mi][nj], ah[mi], bb[nj][0], bb[nj][1]);  // hh
                    MMA16816(acc[mi][nj], al[mi], bb[nj][0], bb[nj][1]);  // lh
                }
#pragma unroll
            for (int p = 0; p < 4; ++p) {
                const int row = wn * 64 + p * 16 + (lane >> 4) * 8 + (lane & 7);
                const int cc  = kk * 2 + ((lane >> 3) & 1);
                const uint32_t off = row * 64 + ((cc ^ ((row >> 1) & 3)) << 4);
                LDSM4(bb[p * 2][0], bb[p * 2][1], bb[p * 2 + 1][0], bb[p * 2 + 1][1],
                      buf + 3 * TILE_B + off);
            }
#pragma unroll
            for (int mi = 0; mi < 4; ++mi)
#pragma unroll
                for (int nj = 0; nj < 8; ++nj)
                    MMA16816(acc[mi][nj], ah[mi], bb[nj][0], bb[nj][1]);  // hl
        }
    }

    const int g = lane >> 2, t = lane & 3;
#pragma unroll
    for (int mi = 0; mi < 4; ++mi) {
#pragma unroll
        for (int nj = 0; nj < 8; ++nj) {
            const int r_ = row0 + wm * 64 + mi * 16 + g;
            const int c_ = col0 + wn * 64 + nj * 8 + 2 * t;
            float2 v, v2;
            v.x  = alpha * acc[mi][nj][0];
            v.y  = alpha * acc[mi][nj][1];
            v2.x = alpha * acc[mi][nj][2];
            v2.y = alpha * acc[mi][nj][3];
            if (BETA) {
                float2 o  = *reinterpret_cast<const float2*>(&C[(size_t)r_ * ldc + c_]);
                float2 o2 = *reinterpret_cast<const float2*>(&C[(size_t)(r_ + 8) * ldc + c_]);
                v.x += o.x;  v.y += o.y;
                v2.x += o2.x; v2.y += o2.y;
            }
            if (ADDI) {
                if (r_ == c_)     v.x  += 1.f;
                if (r_ == c_ + 1) v.y  += 1.f;
                if (r_ + 8 == c_)     v2.x += 1.f;
                if (r_ + 8 == c_ + 1) v2.y += 1.f;
            }
            *reinterpret_cast<float2*>(&C[(size_t)r_ * ldc + c_])       = v;
            *reinterpret_cast<float2*>(&C[(size_t)(r_ + 8) * ldc + c_]) = v2;
        }
    }
}

// ============================================================================
// Row-normalize U -> Vn, RHS = 2*Vn
// ============================================================================
__global__ void normalize_kernel(const float* __restrict__ U) {
    int row = blockIdx.x;
    const float* u = U + (size_t)row * D_DIM;
    __shared__ float red[256];
    float s = 0.f;
    for (int c = threadIdx.x; c < D_DIM; c += 256) { float v = u[c]; s += v * v; }
    red[threadIdx.x] = s;
    __syncthreads();
    for (int off = 128; off > 0; off >>= 1) {
        if (threadIdx.x < off) red[threadIdx.x] += red[threadIdx.x + off];
        __syncthreads();
    }
    float inv = rsqrtf(red[0]);
    for (int c = threadIdx.x; c < D_DIM; c += 256) {
        float v = u[c] * inv;
        g_Vn [(size_t)row * D_DIM + c] = v;
        g_RHS[(size_t)row * D_DIM + c] = 2.f * v;
    }
}

// ============================================================================
// fp32 -> bf16 hi|lo conversions
// ============================================================================
// Row-major: in [R, C] -> out [R, 2C] (hi | lo)
__global__ void conv_hl(const float* __restrict__ in, __nv_bfloat16* __restrict__ out, int C) {
    int r = blockIdx.y;
    int c = blockIdx.x * 256 + threadIdx.x;
    float x = in[(size_t)r * C + c];
    __nv_bfloat16 h = __float2bfloat16(x);
    out[(size_t)r * 2 * C + c]     = h;
    out[(size_t)r * 2 * C + C + c] = __float2bfloat16(x - __bfloat162float(h));
}
// Transposed + split: in [R, C] -> out rows c: hi at [c][outcol0 + r], lo at
// [c][looff + outcol0 + r], row pitch outld.  z-batched via zIn/zOut strides.
__global__ void conv_hl_T_gen(const float* __restrict__ in, int R, int C,
                              __nv_bfloat16* __restrict__ out, int outld,
                              int outcol0, int looff,
                              long long zIn, long long zOut) {
    in  += zIn  * blockIdx.z;
    out += zOut * blockIdx.z;
    __shared__ float t[32][33];
    int r0 = blockIdx.y * 32, c0 = blockIdx.x * 32;
    int tx = threadIdx.x, ty = threadIdx.y;
    for (int i = 0; i < 32; i += 8)
        t[ty + i][tx] = in[(size_t)(r0 + ty + i) * C + c0 + tx];
    __syncthreads();
    for (int i = 0; i < 32; i += 8) {
        float x = t[tx][ty + i];
        __nv_bfloat16 h = __float2bfloat16(x);
        size_t o = (size_t)(c0 + ty + i) * outld + outcol0 + r0 + tx;
        out[o] = h;
        out[(size_t)(c0 + ty + i) * outld + looff + outcol0 + r0 + tx] =
            __float2bfloat16(x - __bfloat162float(h));
    }
}

// ============================================================================
// Diag-block inversion (unit lower tri, 128x128, one CTA each)
// ============================================================================
#define INV_SMEM (2 * NB * (NB + 1) * (int)sizeof(float))
__global__ void invert_diag_kernel() {
    extern __shared__ float sm[];
    float (*Gs)[NB + 1] = (float (*)[NB + 1])sm;
    float (*Zs)[NB + 1] = (float (*)[NB + 1])(sm + NB * (NB + 1));
    const int b0 = blockIdx.x * NB;
    const int tid = threadIdx.x;
    for (int idx = tid; idx < NB * NB; idx += 256) {
        int r = idx >> 7, c = idx & 127;
        Gs[r][c] = g_G[(size_t)(b0 + r) * D_DIM + b0 + c];
        Zs[r][c] = (r == c) ? 1.f : 0.f;
    }
    __syncthreads();
    for (int j = 0; j < NB - 1; ++j) {
        int rows = NB - 1 - j;
        for (int idx = tid; idx < rows * NB; idx += 256) {
            int r = j + 1 + (idx >> 7);
            int c = idx & 127;
            Zs[r][c] -= 2.f * Gs[r][j] * Zs[j][c];
        }
        __syncthreads();
    }
    float* out = g_Tinv + (size_t)blockIdx.x * NB * NB;
    for (int idx = tid; idx < NB * NB; idx += 256) {
        int r = idx >> 7, c = idx & 127;
        out[(size_t)r * NB + c] = Zs[r][c];
    }
}

// ============================================================================
// Pair-combine: 7 Tinv2 blocks (256x256) from 14 inverted 128 blocks.
// ============================================================================
#define CMB_SMEM (3 * 128 * 129 * (int)sizeof(float))
__global__ void __launch_bounds__(256, 1) combine_tinv() {
    extern __shared__ float sm[];
    float (*Abuf)[129] = (float (*)[129])sm;
    float (*Bbuf)[129] = (float (*)[129])(sm + 128 * 129);
    float (*Tm)[129]   = (float (*)[129])(sm + 2 * 128 * 129);
    const int p = blockIdx.x;
    const int tid = threadIdx.x;
    const int trow = (tid / 16) * 8;
    const int tcol = (tid % 16) * 8;
    const float* InvA = g_Tinv + (size_t)(2 * p)     * NB * NB;
    const float* InvB = g_Tinv + (size_t)(2 * p + 1) * NB * NB;
    const size_t g21 = (size_t)(p * 256 + 128) * D_DIM + p * 256;

    for (int idx = tid; idx < 128 * 128; idx += 256) {
        int r = idx >> 7, c = idx & 127;
        Abuf[r][c] = 2.f * g_G[g21 + (size_t)r * D_DIM + c];
        Bbuf[r][c] = InvA[idx];
    }
    __syncthreads();
    {
        float acc[8][8];
#pragma unroll
        for (int i = 0; i < 8; i++)
#pragma unroll
            for (int j = 0; j < 8; j++) acc[i][j] = 0.f;
        for (int k = 0; k < 128; ++k) {
            float a[8], b[8];
#pragma unroll
            for (int i = 0; i < 8; i++) a[i] = Abuf[trow + i][k];
#pragma unroll
            for (int j = 0; j < 8; j++) b[j] = Bbuf[k][tcol + j];
#pragma unroll
            for (int i = 0; i < 8; i++)
#pragma unroll
                for (int j = 0; j < 8; j++) acc[i][j] += a[i] * b[j];
        }
        __syncthreads();
#pragma unroll
        for (int i = 0; i < 8; i++)
#pragma unroll
            for (int j = 0; j < 8; j++) Tm[trow + i][tcol + j] = acc[i][j];
    }
    __syncthreads();
    for (int idx = tid; idx < 128 * 128; idx += 256) {
        int r = idx >> 7, c = idx & 127;
        Abuf[r][c] = InvB[idx];
    }
    __syncthreads();
    float* out = g_Tinv2 + (size_t)p * NB2 * NB2;
    {
        float acc[8][8];
#pragma unroll
        for (int i = 0; i < 8; i++)
#pragma unroll
            for (int j = 0; j < 8; j++) acc[i][j] = 0.f;
        for (int k = 0; k < 128; ++k) {
            float a[8], b[8];
#pragma unroll
            for (int i = 0; i < 8; i++) a[i] = Abuf[trow + i][k];
#pragma unroll
            for (int j = 0; j < 8; j++) b[j] = Tm[k][tcol + j];
#pragma unroll
            for (int i = 0; i < 8; i++)
#pragma unroll
                for (int j = 0; j < 8; j++) acc[i][j] += a[i] * b[j];
        }
#pragma unroll
        for (int i = 0; i < 8; i++) {
#pragma unroll
            for (int j = 0; j < 8; j++) {
                int r = trow + i, c = tcol + j;
                out[(size_t)r * NB2 + c]               = Bbuf[r][c];
                out[(size_t)r * NB2 + 128 + c]         = 0.f;
                out[(size_t)(128 + r) * NB2 + c]       = -acc[i][j];
                out[(size_t)(128 + r) * NB2 + 128 + c] = Abuf[r][c];
            }
        }
    }
}

// ============================================================================
extern "C" void kernel_launch(void* const* d_in, const int* in_sizes, int n_in,
                              void* d_out, int out_size)
{
    const float* X;
    const float* U;
    if (in_sizes[0] == D_DIM * D_DIM && in_sizes[1] != D_DIM * D_DIM) {
        U = (const float*)d_in[0]; X = (const float*)d_in[1];
    } else {
        X = (const float*)d_in[0]; U = (const float*)d_in[1];
    }
    float* out = (float*)d_out;

    float *Vn, *G, *RHS, *Wt, *P, *Tinv2, *S;
    cudaGetSymbolAddress((void**)&Vn,    g_Vn);
    cudaGetSymbolAddress((void**)&G,     g_G);
    cudaGetSymbolAddress((void**)&RHS,   g_RHS);
    cudaGetSymbolAddress((void**)&Wt,    g_Wt);
    cudaGetSymbolAddress((void**)&P,     g_P);
    cudaGetSymbolAddress((void**)&Tinv2, g_Tinv2);
    cudaGetSymbolAddress((void**)&S,     g_S);
    __nv_bfloat16 *Vn_hl, *VnT_hl, *G_hl, *WtT_hl, *RHST_hl, *P_hl, *XT_hl;
    __nv_bfloat16 *Tinv2_hl, *Tinv2T_hl, *S_hl;
    cudaGetSymbolAddress((void**)&Vn_hl,     g_Vn_hl);
    cudaGetSymbolAddress((void**)&VnT_hl,    g_VnT_hl);
    cudaGetSymbolAddress((void**)&G_hl,      g_G_hl);
    cudaGetSymbolAddress((void**)&WtT_hl,    g_WtT_hl);
    cudaGetSymbolAddress((void**)&RHST_hl,   g_RHST_hl);
    cudaGetSymbolAddress((void**)&P_hl,      g_P_hl);
    cudaGetSymbolAddress((void**)&XT_hl,     g_XT_hl);
    cudaGetSymbolAddress((void**)&Tinv2_hl,  g_Tinv2_hl);
    cudaGetSymbolAddress((void**)&Tinv2T_hl, g_Tinv2T_hl);
    cudaGetSymbolAddress((void**)&S_hl,      g_S_hl);

    cudaFuncSetAttribute(invert_diag_kernel,
                         cudaFuncAttributeMaxDynamicSharedMemorySize, INV_SMEM);
    cudaFuncSetAttribute(combine_tinv,
                         cudaFuncAttributeMaxDynamicSharedMemorySize, CMB_SMEM);
    cudaFuncSetAttribute(mma_gemm<0,1,0,0,0>,
                         cudaFuncAttributeMaxDynamicSharedMemorySize, GEMM_SMEM);
    cudaFuncSetAttribute(mma_gemm<0,0,0,0,1>,
                         cudaFuncAttributeMaxDynamicSharedMemorySize, GEMM_SMEM);
    cudaFuncSetAttribute(mma_gemm<0,0,1,0,0>,
                         cudaFuncAttributeMaxDynamicSharedMemorySize, GEMM_SMEM);
    cudaFuncSetAttribute(mma_gemm<0,0,0,1,0>,
                         cudaFuncAttributeMaxDynamicSharedMemorySize, GEMM_SMEM);
    cudaFuncSetAttribute(mma_gemm<1,0,0,0,0>,
                         cudaFuncAttributeMaxDynamicSharedMemorySize, GEMM_SMEM);
    cudaFuncSetAttribute(mma_gemm<0,0,0,0,0>,
                         cudaFuncAttributeMaxDynamicSharedMemorySize, GEMM_SMEM);

    const dim3 t32x8(32, 8);
    const int D2 = 2 * D_DIM;   // 3584

    // X^T split: [D,B] -> XT_hl [B, 2D]
    conv_hl_T_gen<<<dim3(B_DIM / 32, D_DIM / 32), t32x8>>>(
        X, D_DIM, B_DIM, XT_hl, D2, 0, D_DIM, 0, 0);

    // Vn, RHS = 2*Vn; splits of Vn
    normalize_kernel<<<D_DIM, 256>>>(U);
    conv_hl<<<dim3(D_DIM / 256, D_DIM), 256>>>(Vn, Vn_hl, D_DIM);
    conv_hl_T_gen<<<dim3(D_DIM / 32, D_DIM / 32), t32x8>>>(
        Vn, D_DIM, D_DIM, VnT_hl, D2, 0, D_DIM, 0, 0);

    // G = Vn @ Vn^T (lower-triangular tiles)
    mma_gemm<0,1,0,0,0><<<NBLK * (NBLK + 1) / 2, GEMM_THR, GEMM_SMEM>>>(
        Vn_hl, Vn_hl, G, D_DIM, D2, D_DIM, D2, D_DIM, D_DIM, 1.f, 0, 0, 0, D_DIM, 0);
    conv_hl<<<dim3(D_DIM / 256, D_DIM), 256>>>(G, G_hl, D_DIM);

    // Invert diag 128-blocks; combine into 7 Tinv2 256-blocks; split both ways
    invert_diag_kernel<<<NBLK, 256, INV_SMEM>>>();
    combine_tinv<<<NBLK2, 256, CMB_SMEM>>>();
    conv_hl<<<dim3(1, NBLK2 * NB2), 256>>>(Tinv2, Tinv2_hl, NB2);
    conv_hl_T_gen<<<dim3(NB2 / 32, NB2 / 32, NBLK2), t32x8>>>(
        Tinv2, NB2, NB2, Tinv2T_hl, 2 * NB2, 0, NB2,
        (long long)NB2 * NB2, (long long)NB2 * 2 * NB2);

    // S_i = 2 * G[(i+1)*256:, i*256 blk] @ Tinv2_i^T  — one z-batched launch
    mma_gemm<0,0,0,0,1><<<dim3(NB2 / 128, MREM0 / 128, NBLK2 - 1), GEMM_THR, GEMM_SMEM>>>(
        G_hl + (size_t)NB2 * D2, Tinv2T_hl, S,
        NB2, D2, D_DIM, 2 * NB2, NB2, NB2, 2.f,
        (long long)NB2 * D2 + NB2,            // A: down 256 rows, right 256 cols
        (long long)NB2 * 2 * NB2,             // B: next Tinv2T block
        (long long)MREM0 * NB2,               // C: next S block
        MREM0, NB2);
    conv_hl<<<dim3(1, (NBLK2 - 1) * MREM0), 256>>>(S, S_hl, NB2);

    // Chain: per block, finalize RHS^T slice, then trailing update via S_i
    for (int i = 0; i < NBLK2; ++i) {
        conv_hl_T_gen<<<dim3(D_DIM / 32, NB2 / 32), t32x8>>>(
            RHS + (size_t)i * NB2 * D_DIM, NB2, D_DIM,
            RHST_hl, D2, i * NB2, D_DIM, 0, 0);
        int mrem = D_DIM - (i + 1) * NB2;
        if (mrem > 0) {
            mma_gemm<0,0,1,0,0><<<dim3(D_DIM / 128, mrem / 128), GEMM_THR, GEMM_SMEM>>>(
                S_hl + (size_t)i * MREM0 * 2 * NB2,
                RHST_hl + (size_t)i * NB2,
                RHS + (size_t)(i + 1) * NB2 * D_DIM,
                NB2, 2 * NB2, NB2, D2, D_DIM, D_DIM, -1.f, 0, 0, 0, mrem, 0);
        }
    }

    // Wt = blockdiag(Tinv2) @ RHS  — one block-diagonal launch
    mma_gemm<0,0,0,1,0><<<dim3(D_DIM / 128, D_DIM / 128), GEMM_THR, GEMM_SMEM>>>(
        Tinv2_hl, RHST_hl, Wt,
        NB2, 2 * NB2, NB2, D2, D_DIM, D_DIM, 1.f, 0, 0, 0, D_DIM, 0);
    conv_hl_T_gen<<<dim3(D_DIM / 32, D_DIM / 32), t32x8>>>(
        Wt, D_DIM, D_DIM, WtT_hl, D2, 0, D_DIM, 0, 0);

    // P = I - Wt^T @ Vn
    mma_gemm<1,0,0,0,0><<<dim3(D_DIM / 128, D_DIM / 128), GEMM_THR, GEMM_SMEM>>>(
        WtT_hl, VnT_hl, P, D_DIM, D2, D_DIM, D2, D_DIM, D_DIM, -1.f, 0, 0, 0, D_DIM, 0);
    conv_hl<<<dim3(D_DIM / 256, D_DIM), 256>>>(P, P_hl, D_DIM);

    // out = P @ X
    mma_gemm<0,0,0,0,0><<<dim3(B_DIM / 128, D_DIM / 128), GEMM_THR, GEMM_SMEM>>>(
        P_hl, XT_hl, out, D_DIM, D2, D_DIM, D2, D_DIM, B_DIM, 1.f, 0, 0, 0, D_DIM, 0);

    (void)n_in; (void)out_size;
}